// round 9
// baseline (speedup 1.0000x reference)
#include <cuda_runtime.h>
#include <cuda_fp16.h>
#include <cstdint>

#define BB 4
#define NN 4096
#define FF 128
#define ALPHA 0.1f
#define KC 64
#define MT 64          // rows per CTA

// ---------------- device scratch ----------------
__device__ float g_w1[FF], g_w2[FF], g_c[2];
__device__ __align__(16) float2 g_e1[BB * NN];   // (exp(wh1), exp(0.1*wh1))
__device__ __align__(16) float2 g_e2[BB * NN];   // (exp(wh2), exp(0.1*wh2))
__device__ float g_h[BB * NN * FF];                             // 8 MB
__device__ __align__(16) __half g_vph[BB * NN * FF];            // 4 MB fp16 [b][j][f]
__device__ __align__(16) uint32_t g_adjbits[BB * NN * (NN/32)]; // 8.4 MB bitmask

__device__ __forceinline__ float leaky(float x) { return fmaxf(x, ALPHA * x); }

// ---------------- mma.sync helpers ----------------
__device__ __forceinline__ void mma16816(float* d, const uint32_t* a, const uint32_t* b) {
    asm volatile("mma.sync.aligned.m16n8k16.row.col.f32.f16.f16.f32 "
        "{%0,%1,%2,%3},{%4,%5,%6,%7},{%8,%9},{%0,%1,%2,%3};"
        : "+f"(d[0]), "+f"(d[1]), "+f"(d[2]), "+f"(d[3])
        : "r"(a[0]), "r"(a[1]), "r"(a[2]), "r"(a[3]), "r"(b[0]), "r"(b[1]));
}
__device__ __forceinline__ void ldsm_x4(uint32_t* r, uint32_t addr) {
    asm volatile("ldmatrix.sync.aligned.m8n8.x4.shared.b16 {%0,%1,%2,%3},[%4];"
        : "=r"(r[0]), "=r"(r[1]), "=r"(r[2]), "=r"(r[3]) : "r"(addr));
}
__device__ __forceinline__ void ldsm_x4_t(uint32_t* r, uint32_t addr) {
    asm volatile("ldmatrix.sync.aligned.m8n8.x4.trans.shared.b16 {%0,%1,%2,%3},[%4];"
        : "=r"(r[0]), "=r"(r[1]), "=r"(r[2]), "=r"(r[3]) : "r"(addr));
}
__device__ __forceinline__ uint32_t smem_u32(const void* p) {
    uint32_t a;
    asm("{ .reg .u64 t; cvta.to.shared.u64 t, %1; cvt.u32.u64 %0, t; }" : "=r"(a) : "l"(p));
    return a;
}
__device__ __forceinline__ void cp16(uint32_t dst, const void* src) {
    asm volatile("cp.async.cg.shared.global [%0], [%1], 16;" :: "r"(dst), "l"(src) : "memory");
}
#define CP_COMMIT() asm volatile("cp.async.commit_group;" ::: "memory")
#define CP_WAIT0()  asm volatile("cp.async.wait_group 0;" ::: "memory")
__device__ __forceinline__ uint32_t h2u(__half2 h) { return *(uint32_t*)&h; }

// ---------------- kernel 0: pack adj into bitmask (vectorized) -------------
__global__ void __launch_bounds__(256) k_pack(const int* __restrict__ adj) {
    int t = blockIdx.x * 256 + threadIdx.x;
    const int4* p = (const int4*)adj + (size_t)t * 2;
    int4 a = p[0], b = p[1];
    uint32_t bits =
        (uint32_t)(a.x != 0)        | ((uint32_t)(a.y != 0) << 1) |
        ((uint32_t)(a.z != 0) << 2) | ((uint32_t)(a.w != 0) << 3) |
        ((uint32_t)(b.x != 0) << 4) | ((uint32_t)(b.y != 0) << 5) |
        ((uint32_t)(b.z != 0) << 6) | ((uint32_t)(b.w != 0) << 7);
    int lane = threadIdx.x & 31;
    uint32_t my = bits << ((lane & 3) * 8);
    my |= __shfl_xor_sync(0xffffffffu, my, 1);
    my |= __shfl_xor_sync(0xffffffffu, my, 2);
    if ((lane & 3) == 0) g_adjbits[t >> 2] = my;
}

// ---------------- kernel 1: fold a into Q/K projections ----------------
__global__ void k_prep(const float* __restrict__ Wq_w, const float* __restrict__ Wq_b,
                       const float* __restrict__ Wk_w, const float* __restrict__ Wk_b,
                       const float* __restrict__ a) {
    int f = threadIdx.x;
    float s1 = 0.f, s2 = 0.f;
    for (int o = 0; o < FF; o++) {
        s1 += Wq_w[o * FF + f] * a[o];
        s2 += Wk_w[o * FF + f] * a[FF + o];
    }
    g_w1[f] = s1; g_w2[f] = s2;
    if (f == 0) {
        float c1 = 0.f, c2 = 0.f;
        for (int o = 0; o < FF; o++) { c1 += Wq_b[o] * a[o]; c2 += Wk_b[o] * a[FF + o]; }
        g_c[0] = c1; g_c[1] = c2;
    }
}

// ---------------- kernel 2: Wh -> (exp(wh), exp(0.1 wh)) pairs -------------
__global__ void k_wh(const float* __restrict__ q, const float* __restrict__ k) {
    int warp = threadIdx.x >> 5, lane = threadIdx.x & 31;
    int row = blockIdx.x * 8 + warp;
    const float* src; const float* w; float c; float2* dst; int r;
    if (row < BB * NN) { src = q; w = g_w1; c = g_c[0]; dst = g_e1; r = row; }
    else               { src = k; w = g_w2; c = g_c[1]; dst = g_e2; r = row - BB * NN; }
    float4 x  = ((const float4*)(src + (size_t)r * FF))[lane];
    float4 ww = ((const float4*)w)[lane];
    float s = x.x * ww.x + x.y * ww.y + x.z * ww.z + x.w * ww.w;
    #pragma unroll
    for (int o = 16; o > 0; o >>= 1) s += __shfl_xor_sync(0xffffffffu, s, o);
    if (lane == 0) {
        float wh = s + c;
        dst[r] = make_float2(__expf(wh), __expf(ALPHA * wh));
    }
}

// ---------------- kernel 3/5: 128x128 projection GEMM ----------------
__global__ void __launch_bounds__(256)
k_gemm128(const float* __restrict__ in, const float* __restrict__ W,
          const float* __restrict__ bias, float* __restrict__ outf, int mode) {
    __shared__ __align__(16) float in_s[32][33];
    __shared__ __align__(16) float wt_s[32][132];
    int t = threadIdx.x;
    int i0 = blockIdx.x * 32;
    int w = t >> 5, l = t & 31;
    float acc[4][4] = {};
    for (int kt = 0; kt < FF; kt += 32) {
        __syncthreads();
        {
            int r = t >> 3, f4 = t & 7;
            float4 v = *(const float4*)(in + (size_t)(i0 + r) * FF + kt + f4 * 4);
            in_s[r][f4 * 4 + 0] = v.x; in_s[r][f4 * 4 + 1] = v.y;
            in_s[r][f4 * 4 + 2] = v.z; in_s[r][f4 * 4 + 3] = v.w;
        }
        #pragma unroll
        for (int kk = 0; kk < 4; kk++) {
            int idx = t + kk * 256;
            int o = idx >> 3, f4 = idx & 7;
            float4 v = *(const float4*)(W + (size_t)o * FF + kt + f4 * 4);
            wt_s[f4 * 4 + 0][o] = v.x; wt_s[f4 * 4 + 1][o] = v.y;
            wt_s[f4 * 4 + 2][o] = v.z; wt_s[f4 * 4 + 3][o] = v.w;
        }
        __syncthreads();
        #pragma unroll
        for (int f = 0; f < 32; f++) {
            float4 wv = *(const float4*)&wt_s[f][l * 4];
            #pragma unroll
            for (int r = 0; r < 4; r++) {
                float iv = in_s[w * 4 + r][f];
                acc[r][0] += iv * wv.x; acc[r][1] += iv * wv.y;
                acc[r][2] += iv * wv.z; acc[r][3] += iv * wv.w;
            }
        }
    }
    float4 bv = make_float4(0.f, 0.f, 0.f, 0.f);
    if (mode == 1) bv = *(const float4*)(bias + l * 4);
    #pragma unroll
    for (int r = 0; r < 4; r++) {
        float4 o4;
        o4.x = acc[r][0] + bv.x; o4.y = acc[r][1] + bv.y;
        o4.z = acc[r][2] + bv.z; o4.w = acc[r][3] + bv.w;
        size_t base = (size_t)(i0 + w * 4 + r) * FF + l * 4;
        if (mode == 0) {
            o4.x = leaky(o4.x); o4.y = leaky(o4.y); o4.z = leaky(o4.z); o4.w = leaky(o4.w);
            *(float4*)(outf + base) = o4;
        } else {
            __half2 h01 = __floats2half2_rn(o4.x, o4.y);
            __half2 h23 = __floats2half2_rn(o4.z, o4.w);
            *(uint2*)(g_vph + base) = make_uint2(h2u(h01), h2u(h23));
        }
    }
}

// ---------------- kernel 4: masked softmax-agg, M=64 tiles, 2 CTAs/SM ------
#define PSTRIDE 144          // 64 halves + 8 pad
#define PBUF 9216            // 64 * 144
#define VSTRIDE 272
#define VBUF 17408           // 64 * 272
#define PH_BASE 0            // 2 x 9216   -> 18432
#define VH_BASE 18432        // 2 x 17408  -> 53248
#define E2_OFF  53248        // 4096 float2 = 32768 -> 86016
#define RS_OFF  86016        // 256 floats -> 87040
#define IV_OFF  87040        // 64 floats  -> 87296
#define SM_TOTAL 87296

__global__ void __launch_bounds__(256, 2)
k_attn_mma() {
    extern __shared__ char sm[];
    int t = threadIdx.x;
    int lane = t & 31, wid = t >> 5;
    int b = blockIdx.y;
    int it0 = blockIdx.x * MT;

    int mwarp = (wid >> 2) * 32;     // 2 warp-rows x 32 rows
    int nwarp = (wid & 3) * 32;      // 4 warp-cols x 32 cols

    uint32_t sbase = smem_u32(sm);
    uint32_t aoffH = sbase + PH_BASE + (uint32_t)(mwarp + (lane & 15)) * PSTRIDE + (lane >> 4) * 16;
    uint32_t boffH = sbase + VH_BASE + (uint32_t)(lane & 15) * VSTRIDE + (nwarp + (lane >> 4) * 8) * 2;

    // P-gen mapping: 4 threads per row, 16 j's each
    int prow = t >> 2;
    int pq = t & 3;
    float2 e1 = g_e1[b * NN + it0 + prow];
    float ea = e1.x, ea2 = e1.y;
    const uint32_t* maskp = g_adjbits + (size_t)(b * NN + it0 + prow) * (NN / 32) + (pq >> 1);
    int msh = (pq & 1) * 16;
    const __half* vph = g_vph + (size_t)b * NN * FF;
    char* pdstH = sm + PH_BASE + prow * PSTRIDE + pq * 32;
    // e2 pairs for this thread's 16-j quarter: float4 units
    const float4* e2q = (const float4*)(sm + E2_OFF) + pq * 8;

    // V cp.async mapping: 4 threads per row, 4 x 16B each
    int vr = t >> 2, vs = t & 3;
    uint32_t vdst = sbase + VH_BASE + vr * VSTRIDE + vs * 64;
    const __half* vsrc0 = vph + (size_t)vr * FF + vs * 32;

    // stage e2 pairs for this batch (2048 float4, 8/thread)
    {
        float4* d = (float4*)(sm + E2_OFF);
        const float4* s = (const float4*)(g_e2 + b * NN);
        #pragma unroll
        for (int kk = 0; kk < 8; kk++) d[t + kk * 256] = s[t + kk * 256];
    }

    float acc[2][4][4];
    #pragma unroll
    for (int mi = 0; mi < 2; mi++)
        #pragma unroll
        for (int n8 = 0; n8 < 4; n8++)
            #pragma unroll
            for (int x = 0; x < 4; x++) acc[mi][n8][x] = 0.f;
    float rs = 0.f;

    uint2 hiR[4];

    // genP: 16 j's; p = mask ? max(ea*E2, ea2*E2a) : 0
    auto genP = [&](int c, uint32_t mask16) {
        #pragma unroll
        for (int qq = 0; qq < 4; qq++) {
            float4 A  = e2q[c * 32 + qq * 2];       // (E2 j0, E2a j0, E2 j1, E2a j1)
            float4 Bq = e2q[c * 32 + qq * 2 + 1];   // j2, j3
            float p0 = (mask16 >> (qq * 4 + 0)) & 1u ? fmaxf(ea * A.x,  ea2 * A.y)  : 0.f;
            float p1 = (mask16 >> (qq * 4 + 1)) & 1u ? fmaxf(ea * A.z,  ea2 * A.w)  : 0.f;
            float p2 = (mask16 >> (qq * 4 + 2)) & 1u ? fmaxf(ea * Bq.x, ea2 * Bq.y) : 0.f;
            float p3 = (mask16 >> (qq * 4 + 3)) & 1u ? fmaxf(ea * Bq.z, ea2 * Bq.w) : 0.f;
            rs += (p0 + p1) + (p2 + p3);
            __half2 h01 = __floats2half2_rn(p0, p1);
            __half2 h23 = __floats2half2_rn(p2, p3);
            hiR[qq] = make_uint2(h2u(h01), h2u(h23));
        }
    };
    auto storeP = [&](int buf) {
        char* dh = pdstH + buf * PBUF;
        #pragma unroll
        for (int qq = 0; qq < 4; qq++)
            *(uint2*)(dh + qq * 8) = hiR[qq];
    };
    auto loadV = [&](int buf, int j0) {
        const __half* s = vsrc0 + (size_t)j0 * FF;
        uint32_t d = vdst + buf * VBUF;
        #pragma unroll
        for (int kk = 0; kk < 4; kk++)
            cp16(d + kk * 16, s + kk * 8);
        CP_COMMIT();
    };

    // masks: word index = c*2 + (pq>>1)
    uint32_t mA = (__ldg(maskp) >> msh) & 0xffffu;
    uint32_t mB = (__ldg(maskp + 2) >> msh) & 0xffffu;
    loadV(0, 0);
    __syncthreads();                      // e2 staged
    genP(0, mA);
    storeP(0);
    CP_WAIT0();
    __syncthreads();

    for (int c = 0; c < NN / KC; c++) {
        int buf = c & 1, nbuf = buf ^ 1;
        bool has_next = (c + 1) < (NN / KC);
        uint32_t mC = 0;
        if (c + 2 < NN / KC)
            mC = (__ldg(maskp + (size_t)(c + 2) * 2) >> msh) & 0xffffu;
        if (has_next) {
            loadV(nbuf, (c + 1) * KC);
            genP(c + 1, mB);
        }
        // ---- MMA on buffer `buf`: 4 k16 steps ----
        uint32_t pb = aoffH + buf * PBUF;
        uint32_t vb = boffH + buf * VBUF;
        #pragma unroll
        for (int kk = 0; kk < 4; kk++) {
            uint32_t ah[2][4];
            ldsm_x4(ah[0], pb + kk * 32);
            ldsm_x4(ah[1], pb + 16 * PSTRIDE + kk * 32);
            #pragma unroll
            for (int nb = 0; nb < 2; nb++) {
                uint32_t bh[4];
                ldsm_x4_t(bh, vb + kk * 16 * VSTRIDE + nb * 32);
                #pragma unroll
                for (int mi = 0; mi < 2; mi++) {
                    mma16816(acc[mi][nb * 2 + 0], ah[mi], bh + 0);
                    mma16816(acc[mi][nb * 2 + 1], ah[mi], bh + 2);
                }
            }
        }
        if (has_next) storeP(nbuf);
        mB = mC;
        CP_WAIT0();
        __syncthreads();
    }

    // ---- normalizers: 4 partial sums per row ----
    ((float*)(sm + RS_OFF))[t] = rs;
    __syncthreads();
    if (t < MT) {
        const float* rss = (const float*)(sm + RS_OFF) + t * 4;
        ((float*)(sm + IV_OFF))[t] = 1.0f / ((rss[0] + rss[1]) + (rss[2] + rss[3]));
    }
    __syncthreads();
    const float* inv = (const float*)(sm + IV_OFF);

    // ---- write h ----
    #pragma unroll
    for (int mi = 0; mi < 2; mi++) {
        int r0 = mwarp + mi * 16 + (lane >> 2);
        float iv0 = inv[r0], iv1 = inv[r0 + 8];
        #pragma unroll
        for (int n8 = 0; n8 < 4; n8++) {
            int col = nwarp + n8 * 8 + (lane & 3) * 2;
            float2 v0 = make_float2(acc[mi][n8][0] * iv0, acc[mi][n8][1] * iv0);
            float2 v1 = make_float2(acc[mi][n8][2] * iv1, acc[mi][n8][3] * iv1);
            *(float2*)(g_h + (size_t)(b * NN + it0 + r0) * FF + col) = v0;
            *(float2*)(g_h + (size_t)(b * NN + it0 + r0 + 8) * FF + col) = v1;
        }
    }
}

// ---------------- launch ----------------
extern "C" void kernel_launch(void* const* d_in, const int* in_sizes, int n_in,
                              void* d_out, int out_size) {
    const float* q    = (const float*)d_in[0];
    const float* k    = (const float*)d_in[1];
    const float* v    = (const float*)d_in[2];
    const int*   adj  = (const int*)  d_in[3];
    const float* Wq_w = (const float*)d_in[4];
    const float* Wq_b = (const float*)d_in[5];
    const float* Wk_w = (const float*)d_in[6];
    const float* Wk_b = (const float*)d_in[7];
    const float* Wv_w = (const float*)d_in[8];
    const float* Wv_b = (const float*)d_in[9];
    const float* a    = (const float*)d_in[10];
    const float* Wo_w = (const float*)d_in[11];
    float* out = (float*)d_out;

    void* h_ptr = nullptr;
    cudaGetSymbolAddress(&h_ptr, g_h);

    cudaFuncSetAttribute(k_attn_mma, cudaFuncAttributeMaxDynamicSharedMemorySize, SM_TOTAL);

    k_pack<<<(BB * NN * NN) / (256 * 8), 256>>>(adj);
    k_prep<<<1, 128>>>(Wq_w, Wq_b, Wk_w, Wk_b, a);
    k_wh<<<(2 * BB * NN) / 8, 256>>>(q, k);
    k_gemm128<<<BB * NN / 32, 256>>>(v, Wv_w, Wv_b, nullptr, 1);
    {
        dim3 grid(NN / MT, BB);
        k_attn_mma<<<grid, 256, SM_TOTAL>>>();
    }
    k_gemm128<<<BB * NN / 32, 256>>>((const float*)h_ptr, Wo_w, nullptr, out, 0);
}

// round 10
// speedup vs baseline: 1.2842x; 1.2842x over previous
#include <cuda_runtime.h>
#include <cuda_fp16.h>
#include <cstdint>

#define BB 4
#define NN 4096
#define FF 128
#define ALPHA 0.1f
#define KC 64

// ---------------- device scratch ----------------
__device__ float g_w1[FF], g_w2[FF], g_c[2];
__device__ __align__(16) float2 g_e1[BB * NN];   // (exp(wh1), exp(0.1*wh1))
__device__ __align__(16) float2 g_e2[BB * NN];   // (exp(wh2), exp(0.1*wh2))
__device__ float g_h[BB * NN * FF];                             // 8 MB
__device__ __align__(16) __half g_vph[BB * NN * FF];            // 4 MB fp16 [b][j][f]
__device__ __align__(16) uint32_t g_adjbits[BB * NN * (NN/32)]; // 8.4 MB bitmask

__device__ __forceinline__ float leaky(float x) { return fmaxf(x, ALPHA * x); }

// ---------------- mma.sync helpers ----------------
__device__ __forceinline__ void mma16816(float* d, const uint32_t* a, const uint32_t* b) {
    asm volatile("mma.sync.aligned.m16n8k16.row.col.f32.f16.f16.f32 "
        "{%0,%1,%2,%3},{%4,%5,%6,%7},{%8,%9},{%0,%1,%2,%3};"
        : "+f"(d[0]), "+f"(d[1]), "+f"(d[2]), "+f"(d[3])
        : "r"(a[0]), "r"(a[1]), "r"(a[2]), "r"(a[3]), "r"(b[0]), "r"(b[1]));
}
__device__ __forceinline__ void ldsm_x4(uint32_t* r, uint32_t addr) {
    asm volatile("ldmatrix.sync.aligned.m8n8.x4.shared.b16 {%0,%1,%2,%3},[%4];"
        : "=r"(r[0]), "=r"(r[1]), "=r"(r[2]), "=r"(r[3]) : "r"(addr));
}
__device__ __forceinline__ void ldsm_x4_t(uint32_t* r, uint32_t addr) {
    asm volatile("ldmatrix.sync.aligned.m8n8.x4.trans.shared.b16 {%0,%1,%2,%3},[%4];"
        : "=r"(r[0]), "=r"(r[1]), "=r"(r[2]), "=r"(r[3]) : "r"(addr));
}
__device__ __forceinline__ uint32_t smem_u32(const void* p) {
    uint32_t a;
    asm("{ .reg .u64 t; cvta.to.shared.u64 t, %1; cvt.u32.u64 %0, t; }" : "=r"(a) : "l"(p));
    return a;
}
__device__ __forceinline__ void cp16(uint32_t dst, const void* src) {
    asm volatile("cp.async.cg.shared.global [%0], [%1], 16;" :: "r"(dst), "l"(src) : "memory");
}
#define CP_COMMIT() asm volatile("cp.async.commit_group;" ::: "memory")
#define CP_WAIT0()  asm volatile("cp.async.wait_group 0;" ::: "memory")
#define BAR_G(id)   asm volatile("bar.sync %0, 256;" :: "r"(id) : "memory")
__device__ __forceinline__ uint32_t h2u(__half2 h) { return *(uint32_t*)&h; }

// ---------------- kernel 0: pack adj into bitmask (vectorized) -------------
__global__ void __launch_bounds__(256) k_pack(const int* __restrict__ adj) {
    int t = blockIdx.x * 256 + threadIdx.x;
    const int4* p = (const int4*)adj + (size_t)t * 2;
    int4 a = p[0], b = p[1];
    uint32_t bits =
        (uint32_t)(a.x != 0)        | ((uint32_t)(a.y != 0) << 1) |
        ((uint32_t)(a.z != 0) << 2) | ((uint32_t)(a.w != 0) << 3) |
        ((uint32_t)(b.x != 0) << 4) | ((uint32_t)(b.y != 0) << 5) |
        ((uint32_t)(b.z != 0) << 6) | ((uint32_t)(b.w != 0) << 7);
    int lane = threadIdx.x & 31;
    uint32_t my = bits << ((lane & 3) * 8);
    my |= __shfl_xor_sync(0xffffffffu, my, 1);
    my |= __shfl_xor_sync(0xffffffffu, my, 2);
    if ((lane & 3) == 0) g_adjbits[t >> 2] = my;
}

// ---------------- kernel 1: fold a into Q/K projections ----------------
__global__ void k_prep(const float* __restrict__ Wq_w, const float* __restrict__ Wq_b,
                       const float* __restrict__ Wk_w, const float* __restrict__ Wk_b,
                       const float* __restrict__ a) {
    int f = threadIdx.x;
    float s1 = 0.f, s2 = 0.f;
    for (int o = 0; o < FF; o++) {
        s1 += Wq_w[o * FF + f] * a[o];
        s2 += Wk_w[o * FF + f] * a[FF + o];
    }
    g_w1[f] = s1; g_w2[f] = s2;
    if (f == 0) {
        float c1 = 0.f, c2 = 0.f;
        for (int o = 0; o < FF; o++) { c1 += Wq_b[o] * a[o]; c2 += Wk_b[o] * a[FF + o]; }
        g_c[0] = c1; g_c[1] = c2;
    }
}

// ---------------- kernel 2: Wh -> (exp(wh), exp(0.1 wh)) pairs -------------
__global__ void k_wh(const float* __restrict__ q, const float* __restrict__ k) {
    int warp = threadIdx.x >> 5, lane = threadIdx.x & 31;
    int row = blockIdx.x * 8 + warp;
    const float* src; const float* w; float c; float2* dst; int r;
    if (row < BB * NN) { src = q; w = g_w1; c = g_c[0]; dst = g_e1; r = row; }
    else               { src = k; w = g_w2; c = g_c[1]; dst = g_e2; r = row - BB * NN; }
    float4 x  = ((const float4*)(src + (size_t)r * FF))[lane];
    float4 ww = ((const float4*)w)[lane];
    float s = x.x * ww.x + x.y * ww.y + x.z * ww.z + x.w * ww.w;
    #pragma unroll
    for (int o = 16; o > 0; o >>= 1) s += __shfl_xor_sync(0xffffffffu, s, o);
    if (lane == 0) {
        float wh = s + c;
        dst[r] = make_float2(__expf(wh), __expf(ALPHA * wh));
    }
}

// ---------------- kernel 3/5: 128x128 projection GEMM ----------------
__global__ void __launch_bounds__(256)
k_gemm128(const float* __restrict__ in, const float* __restrict__ W,
          const float* __restrict__ bias, float* __restrict__ outf, int mode) {
    __shared__ __align__(16) float in_s[32][33];
    __shared__ __align__(16) float wt_s[32][132];
    int t = threadIdx.x;
    int i0 = blockIdx.x * 32;
    int w = t >> 5, l = t & 31;
    float acc[4][4] = {};
    for (int kt = 0; kt < FF; kt += 32) {
        __syncthreads();
        {
            int r = t >> 3, f4 = t & 7;
            float4 v = *(const float4*)(in + (size_t)(i0 + r) * FF + kt + f4 * 4);
            in_s[r][f4 * 4 + 0] = v.x; in_s[r][f4 * 4 + 1] = v.y;
            in_s[r][f4 * 4 + 2] = v.z; in_s[r][f4 * 4 + 3] = v.w;
        }
        #pragma unroll
        for (int kk = 0; kk < 4; kk++) {
            int idx = t + kk * 256;
            int o = idx >> 3, f4 = idx & 7;
            float4 v = *(const float4*)(W + (size_t)o * FF + kt + f4 * 4);
            wt_s[f4 * 4 + 0][o] = v.x; wt_s[f4 * 4 + 1][o] = v.y;
            wt_s[f4 * 4 + 2][o] = v.z; wt_s[f4 * 4 + 3][o] = v.w;
        }
        __syncthreads();
        #pragma unroll
        for (int f = 0; f < 32; f++) {
            float4 wv = *(const float4*)&wt_s[f][l * 4];
            #pragma unroll
            for (int r = 0; r < 4; r++) {
                float iv = in_s[w * 4 + r][f];
                acc[r][0] += iv * wv.x; acc[r][1] += iv * wv.y;
                acc[r][2] += iv * wv.z; acc[r][3] += iv * wv.w;
            }
        }
    }
    float4 bv = make_float4(0.f, 0.f, 0.f, 0.f);
    if (mode == 1) bv = *(const float4*)(bias + l * 4);
    #pragma unroll
    for (int r = 0; r < 4; r++) {
        float4 o4;
        o4.x = acc[r][0] + bv.x; o4.y = acc[r][1] + bv.y;
        o4.z = acc[r][2] + bv.z; o4.w = acc[r][3] + bv.w;
        size_t base = (size_t)(i0 + w * 4 + r) * FF + l * 4;
        if (mode == 0) {
            o4.x = leaky(o4.x); o4.y = leaky(o4.y); o4.z = leaky(o4.z); o4.w = leaky(o4.w);
            *(float4*)(outf + base) = o4;
        } else {
            __half2 h01 = __floats2half2_rn(o4.x, o4.y);
            __half2 h23 = __floats2half2_rn(o4.z, o4.w);
            *(uint2*)(g_vph + base) = make_uint2(h2u(h01), h2u(h23));
        }
    }
}

// ---------------- kernel 4: dual-pipeline masked softmax-agg ----------------
// 512 threads = 2 groups of 8 warps; group g owns j-chunks with c%2==g,
// own double-buffered P/V smem, own named barrier. Merge partial h at end.
#define PSTRIDE 144          // 64 halves + 8 pad (P tile row)
#define PBUF 18432           // 128 * 144
#define VSTRIDE 272          // 128 halves + 8 pad (V tile row)
#define VBUF 17408           // 64 * 272
#define PH_BASE 0            // 2 groups x 2 bufs x PBUF = 73728
#define VH_BASE 73728        // 2 groups x 2 bufs x VBUF = 69632 -> 143360
#define E2_OFF  143360       // 4096 float2 = 32768 -> 176128
#define RS_OFF  176128       // 512 floats -> 178176
#define IV_OFF  178176       // 128 floats -> 178688
#define SM_TOTAL 178688
#define MRG_STRIDE 132       // merge buffer (reuses P area): 128x132 fp32

__global__ void __launch_bounds__(512, 1)
k_attn_mma() {
    extern __shared__ char sm[];
    int t = threadIdx.x;
    int lane = t & 31, wid = t >> 5;
    int g = wid >> 3;                // pipeline group 0/1
    int w8 = wid & 7;
    int t256 = t & 255;
    int b = blockIdx.y;
    int it0 = blockIdx.x * 128;

    int mwarp = (w8 >> 2) * 64;      // 2 warp-rows x 64 rows
    int nwarp = (w8 & 3) * 32;       // 4 warp-cols x 32 cols

    uint32_t sbase = smem_u32(sm);
    uint32_t pgbase = sbase + PH_BASE + g * 2 * PBUF;
    uint32_t vgbase = sbase + VH_BASE + g * 2 * VBUF;
    uint32_t aoff = pgbase + (uint32_t)(mwarp + (lane & 15)) * PSTRIDE + (lane >> 4) * 16;
    uint32_t boff = vgbase + (uint32_t)(lane & 15) * VSTRIDE + (nwarp + (lane >> 4) * 8) * 2;

    // P-gen mapping: 2 threads per row, 32 j's each (within group's chunk)
    int prow = t256 >> 1;
    int jh = (t256 & 1) * 32;
    float2 e1 = g_e1[b * NN + it0 + prow];
    float ea = e1.x, ea2 = e1.y;
    const uint32_t* maskp = g_adjbits + (size_t)(b * NN + it0 + prow) * (NN / 32) + (t256 & 1);
    const __half* vph = g_vph + (size_t)b * NN * FF;
    char* pdstH = sm + PH_BASE + g * 2 * PBUF + prow * PSTRIDE + jh * 2;
    const float4* e2q = (const float4*)(sm + E2_OFF) + (t256 & 1) * 16;

    // V cp.async mapping: 4 threads per row, 4 x 16B each (64-row tile)
    int vr = t256 >> 2, vs = t256 & 3;
    uint32_t vdst = vgbase + vr * VSTRIDE + vs * 64;
    const __half* vsrc0 = vph + (size_t)vr * FF + vs * 32;

    // stage e2 pairs for this batch (2048 float4, 4 per thread)
    {
        float4* d = (float4*)(sm + E2_OFF);
        const float4* s = (const float4*)(g_e2 + b * NN);
        #pragma unroll
        for (int kk = 0; kk < 4; kk++) d[t + kk * 512] = s[t + kk * 512];
    }

    float acc[4][4][4];
    #pragma unroll
    for (int mi = 0; mi < 4; mi++)
        #pragma unroll
        for (int n8 = 0; n8 < 4; n8++)
            #pragma unroll
            for (int x = 0; x < 4; x++) acc[mi][n8][x] = 0.f;
    float rs = 0.f;

    uint2 hiR[8];

    // genP: 32 j's of chunk c; p = mask ? max(ea*E2, ea2*E2a) : 0
    auto genP = [&](int c, uint32_t mask) {
        #pragma unroll
        for (int qq = 0; qq < 8; qq++) {
            float4 A  = e2q[c * 32 + qq * 2];       // (E2 j0, E2a j0, E2 j1, E2a j1)
            float4 Bq = e2q[c * 32 + qq * 2 + 1];   // j2, j3
            float p0 = (mask >> (qq * 4 + 0)) & 1u ? fmaxf(ea * A.x,  ea2 * A.y)  : 0.f;
            float p1 = (mask >> (qq * 4 + 1)) & 1u ? fmaxf(ea * A.z,  ea2 * A.w)  : 0.f;
            float p2 = (mask >> (qq * 4 + 2)) & 1u ? fmaxf(ea * Bq.x, ea2 * Bq.y) : 0.f;
            float p3 = (mask >> (qq * 4 + 3)) & 1u ? fmaxf(ea * Bq.z, ea2 * Bq.w) : 0.f;
            rs += (p0 + p1) + (p2 + p3);
            __half2 h01 = __floats2half2_rn(p0, p1);
            __half2 h23 = __floats2half2_rn(p2, p3);
            hiR[qq] = make_uint2(h2u(h01), h2u(h23));
        }
    };
    auto storeP = [&](int buf) {
        char* dh = pdstH + buf * PBUF;
        #pragma unroll
        for (int qq = 0; qq < 8; qq++)
            *(uint2*)(dh + qq * 8) = hiR[qq];
    };
    auto loadV = [&](int buf, int j0) {
        const __half* s = vsrc0 + (size_t)j0 * FF;
        uint32_t d = vdst + buf * VBUF;
        #pragma unroll
        for (int kk = 0; kk < 4; kk++)
            cp16(d + kk * 16, s + kk * 8);
        CP_COMMIT();
    };

    // ---- prologue: chunk c0 = g ----
    uint32_t mA = __ldg(maskp + 2 * g);
    uint32_t mB = __ldg(maskp + 2 * (g + 2));
    loadV(0, g * KC);
    __syncthreads();                 // e2 staged (both groups)
    genP(g, mA);
    storeP(0);
    CP_WAIT0();
    BAR_G(g + 1);

    const int NIT = NN / KC / 2;     // 32 chunks per group
    for (int i = 0; i < NIT; i++) {
        int c = 2 * i + g;
        int buf = i & 1, nbuf = buf ^ 1;
        bool has_next = (i + 1) < NIT;
        uint32_t mC = 0;
        if (i + 2 < NIT) mC = __ldg(maskp + 2 * (c + 4));
        if (has_next) {
            loadV(nbuf, (c + 2) * KC);
            genP(c + 2, mB);
        }
        // ---- MMA on buffer `buf`: 4 k16 steps, 64 rows x 32 cols per warp --
        uint32_t pb = aoff + buf * PBUF;
        uint32_t vb = boff + buf * VBUF;
        #pragma unroll
        for (int kk = 0; kk < 4; kk++) {
            uint32_t ah[4][4];
            #pragma unroll
            for (int mi = 0; mi < 4; mi++)
                ldsm_x4(ah[mi], pb + mi * 16 * PSTRIDE + kk * 32);
            #pragma unroll
            for (int nb = 0; nb < 2; nb++) {
                uint32_t bh[4];
                ldsm_x4_t(bh, vb + kk * 16 * VSTRIDE + nb * 32);
                #pragma unroll
                for (int mi = 0; mi < 4; mi++) {
                    mma16816(acc[mi][nb * 2 + 0], ah[mi], bh + 0);
                    mma16816(acc[mi][nb * 2 + 1], ah[mi], bh + 2);
                }
            }
        }
        if (has_next) storeP(nbuf);
        mB = mC;
        CP_WAIT0();
        BAR_G(g + 1);
    }

    // ---- merge groups + normalize + write ----
    ((float*)(sm + RS_OFF))[g * 256 + t256] = rs;
    __syncthreads();

    float* mbuf = (float*)sm;        // reuse P area: 128 x 132 fp32
    if (g == 1) {
        #pragma unroll
        for (int mi = 0; mi < 4; mi++) {
            int r0 = mwarp + mi * 16 + (lane >> 2);
            #pragma unroll
            for (int n8 = 0; n8 < 4; n8++) {
                int col = nwarp + n8 * 8 + (lane & 3) * 2;
                *(float2*)&mbuf[r0 * MRG_STRIDE + col] =
                    make_float2(acc[mi][n8][0], acc[mi][n8][1]);
                *(float2*)&mbuf[(r0 + 8) * MRG_STRIDE + col] =
                    make_float2(acc[mi][n8][2], acc[mi][n8][3]);
            }
        }
    } else if (t < 128) {
        const float* rss = (const float*)(sm + RS_OFF);
        float s = (rss[2 * t] + rss[2 * t + 1]) + (rss[256 + 2 * t] + rss[256 + 2 * t + 1]);
        ((float*)(sm + IV_OFF))[t] = 1.0f / s;
    }
    __syncthreads();

    if (g == 0) {
        const float* inv = (const float*)(sm + IV_OFF);
        #pragma unroll
        for (int mi = 0; mi < 4; mi++) {
            int r0 = mwarp + mi * 16 + (lane >> 2);
            float iv0 = inv[r0], iv1 = inv[r0 + 8];
            #pragma unroll
            for (int n8 = 0; n8 < 4; n8++) {
                int col = nwarp + n8 * 8 + (lane & 3) * 2;
                float2 m0 = *(const float2*)&mbuf[r0 * MRG_STRIDE + col];
                float2 m1 = *(const float2*)&mbuf[(r0 + 8) * MRG_STRIDE + col];
                float2 v0 = make_float2((acc[mi][n8][0] + m0.x) * iv0,
                                        (acc[mi][n8][1] + m0.y) * iv0);
                float2 v1 = make_float2((acc[mi][n8][2] + m1.x) * iv1,
                                        (acc[mi][n8][3] + m1.y) * iv1);
                *(float2*)(g_h + (size_t)(b * NN + it0 + r0) * FF + col) = v0;
                *(float2*)(g_h + (size_t)(b * NN + it0 + r0 + 8) * FF + col) = v1;
            }
        }
    }
}

// ---------------- launch ----------------
extern "C" void kernel_launch(void* const* d_in, const int* in_sizes, int n_in,
                              void* d_out, int out_size) {
    const float* q    = (const float*)d_in[0];
    const float* k    = (const float*)d_in[1];
    const float* v    = (const float*)d_in[2];
    const int*   adj  = (const int*)  d_in[3];
    const float* Wq_w = (const float*)d_in[4];
    const float* Wq_b = (const float*)d_in[5];
    const float* Wk_w = (const float*)d_in[6];
    const float* Wk_b = (const float*)d_in[7];
    const float* Wv_w = (const float*)d_in[8];
    const float* Wv_b = (const float*)d_in[9];
    const float* a    = (const float*)d_in[10];
    const float* Wo_w = (const float*)d_in[11];
    float* out = (float*)d_out;

    void* h_ptr = nullptr;
    cudaGetSymbolAddress(&h_ptr, g_h);

    cudaFuncSetAttribute(k_attn_mma, cudaFuncAttributeMaxDynamicSharedMemorySize, SM_TOTAL);

    k_pack<<<(BB * NN * NN) / (256 * 8), 256>>>(adj);
    k_prep<<<1, 128>>>(Wq_w, Wq_b, Wk_w, Wk_b, a);
    k_wh<<<(2 * BB * NN) / 8, 256>>>(q, k);
    k_gemm128<<<BB * NN / 32, 256>>>(v, Wv_w, Wv_b, nullptr, 1);
    {
        dim3 grid(NN / 128, BB);
        k_attn_mma<<<grid, 512, SM_TOTAL>>>();
    }
    k_gemm128<<<BB * NN / 32, 256>>>((const float*)h_ptr, Wo_w, nullptr, out, 0);
}

// round 11
// speedup vs baseline: 1.4610x; 1.1377x over previous
#include <cuda_runtime.h>
#include <cuda_fp16.h>
#include <cstdint>

#define BB 4
#define NN 4096
#define FF 128
#define ALPHA 0.1f
#define KC 64

// ---------------- device scratch ----------------
__device__ float g_w1[FF], g_w2[FF], g_c[2];
__device__ __align__(16) float2 g_e1[BB * NN];   // (exp(wh1), exp(0.1*wh1))
__device__ __align__(16) float2 g_e2[BB * NN];   // (exp(wh2), exp(0.1*wh2))
__device__ float g_h[BB * NN * FF];                             // 8 MB
__device__ __align__(16) __half g_vph[BB * NN * FF];            // 4 MB fp16 [b][j][f]
__device__ __align__(16) uint32_t g_adjbits[BB * NN * (NN/32)]; // 8.4 MB bitmask

__device__ __forceinline__ float leaky(float x) { return fmaxf(x, ALPHA * x); }

// ---------------- mma.sync helpers ----------------
__device__ __forceinline__ void mma16816(float* d, const uint32_t* a, const uint32_t* b) {
    asm volatile("mma.sync.aligned.m16n8k16.row.col.f32.f16.f16.f32 "
        "{%0,%1,%2,%3},{%4,%5,%6,%7},{%8,%9},{%0,%1,%2,%3};"
        : "+f"(d[0]), "+f"(d[1]), "+f"(d[2]), "+f"(d[3])
        : "r"(a[0]), "r"(a[1]), "r"(a[2]), "r"(a[3]), "r"(b[0]), "r"(b[1]));
}
__device__ __forceinline__ void ldsm_x4(uint32_t* r, uint32_t addr) {
    asm volatile("ldmatrix.sync.aligned.m8n8.x4.shared.b16 {%0,%1,%2,%3},[%4];"
        : "=r"(r[0]), "=r"(r[1]), "=r"(r[2]), "=r"(r[3]) : "r"(addr));
}
__device__ __forceinline__ void ldsm_x4_t(uint32_t* r, uint32_t addr) {
    asm volatile("ldmatrix.sync.aligned.m8n8.x4.trans.shared.b16 {%0,%1,%2,%3},[%4];"
        : "=r"(r[0]), "=r"(r[1]), "=r"(r[2]), "=r"(r[3]) : "r"(addr));
}
__device__ __forceinline__ uint32_t smem_u32(const void* p) {
    uint32_t a;
    asm("{ .reg .u64 t; cvta.to.shared.u64 t, %1; cvt.u32.u64 %0, t; }" : "=r"(a) : "l"(p));
    return a;
}
__device__ __forceinline__ void cp16(uint32_t dst, const void* src) {
    asm volatile("cp.async.cg.shared.global [%0], [%1], 16;" :: "r"(dst), "l"(src) : "memory");
}
#define CP_COMMIT() asm volatile("cp.async.commit_group;" ::: "memory")
#define CP_WAIT0()  asm volatile("cp.async.wait_group 0;" ::: "memory")
#define BAR_G(id)   asm volatile("bar.sync %0, 256;" :: "r"(id) : "memory")
__device__ __forceinline__ uint32_t h2u(__half2 h) { return *(uint32_t*)&h; }

// ---------------- kernel 0: pack adj into bitmask (vectorized) -------------
__global__ void __launch_bounds__(256) k_pack(const int* __restrict__ adj) {
    int t = blockIdx.x * 256 + threadIdx.x;
    const int4* p = (const int4*)adj + (size_t)t * 2;
    int4 a = p[0], b = p[1];
    uint32_t bits =
        (uint32_t)(a.x != 0)        | ((uint32_t)(a.y != 0) << 1) |
        ((uint32_t)(a.z != 0) << 2) | ((uint32_t)(a.w != 0) << 3) |
        ((uint32_t)(b.x != 0) << 4) | ((uint32_t)(b.y != 0) << 5) |
        ((uint32_t)(b.z != 0) << 6) | ((uint32_t)(b.w != 0) << 7);
    int lane = threadIdx.x & 31;
    uint32_t my = bits << ((lane & 3) * 8);
    my |= __shfl_xor_sync(0xffffffffu, my, 1);
    my |= __shfl_xor_sync(0xffffffffu, my, 2);
    if ((lane & 3) == 0) g_adjbits[t >> 2] = my;
}

// ---------------- kernel 1: fold a into Q/K projections ----------------
__global__ void k_prep(const float* __restrict__ Wq_w, const float* __restrict__ Wq_b,
                       const float* __restrict__ Wk_w, const float* __restrict__ Wk_b,
                       const float* __restrict__ a) {
    int f = threadIdx.x;
    float s1 = 0.f, s2 = 0.f;
    for (int o = 0; o < FF; o++) {
        s1 += Wq_w[o * FF + f] * a[o];
        s2 += Wk_w[o * FF + f] * a[FF + o];
    }
    g_w1[f] = s1; g_w2[f] = s2;
    if (f == 0) {
        float c1 = 0.f, c2 = 0.f;
        for (int o = 0; o < FF; o++) { c1 += Wq_b[o] * a[o]; c2 += Wk_b[o] * a[FF + o]; }
        g_c[0] = c1; g_c[1] = c2;
    }
}

// ---------------- kernel 2: Wh -> (exp(wh), exp(0.1 wh)) pairs -------------
__global__ void k_wh(const float* __restrict__ q, const float* __restrict__ k) {
    int warp = threadIdx.x >> 5, lane = threadIdx.x & 31;
    int row = blockIdx.x * 8 + warp;
    const float* src; const float* w; float c; float2* dst; int r;
    if (row < BB * NN) { src = q; w = g_w1; c = g_c[0]; dst = g_e1; r = row; }
    else               { src = k; w = g_w2; c = g_c[1]; dst = g_e2; r = row - BB * NN; }
    float4 x  = ((const float4*)(src + (size_t)r * FF))[lane];
    float4 ww = ((const float4*)w)[lane];
    float s = x.x * ww.x + x.y * ww.y + x.z * ww.z + x.w * ww.w;
    #pragma unroll
    for (int o = 16; o > 0; o >>= 1) s += __shfl_xor_sync(0xffffffffu, s, o);
    if (lane == 0) {
        float wh = s + c;
        dst[r] = make_float2(__expf(wh), __expf(ALPHA * wh));
    }
}

// ---------------- kernel 3/5: tensor-core projection GEMM ------------------
// out[i][o] = X[i][f] . W[o][f] (+bias) ; fp16 hi/lo 3-pass, fp32 accum.
// outh != null : write fp16 to outh (V projection, bias added)
// outf != null : write fp32 leaky (output projection)
#define GSTR 272             // bytes per smem row (136 halves)
#define GX_HI 0
#define GX_LO 34816
#define GW_HI 69632
#define GW_LO 104448
#define G_TOTAL 139264

__global__ void __launch_bounds__(256, 1)
k_gemm_tc(const float* __restrict__ in, const float* __restrict__ W,
          const float* __restrict__ bias, float* __restrict__ outf,
          __half* __restrict__ outh) {
    extern __shared__ char sm[];
    int t = threadIdx.x, lane = t & 31, wid = t >> 5;
    int i0 = blockIdx.x * 128;
    uint32_t sb = smem_u32(sm);

    // convert X (128 rows) and W (128 rows) to fp16 hi/lo in smem
    #pragma unroll
    for (int kk = 0; kk < 16; kk++) {
        int e = t + kk * 256;
        int row = e >> 5, f4 = e & 31;
        int off = row * GSTR + f4 * 8;
        float4 xv = *(const float4*)(in + (size_t)(i0 + row) * FF + f4 * 4);
        __half2 xh01 = __floats2half2_rn(xv.x, xv.y);
        __half2 xh23 = __floats2half2_rn(xv.z, xv.w);
        float2 xf01 = __half22float2(xh01), xf23 = __half22float2(xh23);
        __half2 xl01 = __floats2half2_rn(xv.x - xf01.x, xv.y - xf01.y);
        __half2 xl23 = __floats2half2_rn(xv.z - xf23.x, xv.w - xf23.y);
        *(uint2*)(sm + GX_HI + off) = make_uint2(h2u(xh01), h2u(xh23));
        *(uint2*)(sm + GX_LO + off) = make_uint2(h2u(xl01), h2u(xl23));
        float4 wv = *(const float4*)(W + (size_t)row * FF + f4 * 4);
        __half2 wh01 = __floats2half2_rn(wv.x, wv.y);
        __half2 wh23 = __floats2half2_rn(wv.z, wv.w);
        float2 wf01 = __half22float2(wh01), wf23 = __half22float2(wh23);
        __half2 wl01 = __floats2half2_rn(wv.x - wf01.x, wv.y - wf01.y);
        __half2 wl23 = __floats2half2_rn(wv.z - wf23.x, wv.w - wf23.y);
        *(uint2*)(sm + GW_HI + off) = make_uint2(h2u(wh01), h2u(wh23));
        *(uint2*)(sm + GW_LO + off) = make_uint2(h2u(wl01), h2u(wl23));
    }
    __syncthreads();

    int mwarp = (wid >> 2) * 64;     // 2 warp-rows x 64
    int nwarp = (wid & 3) * 32;      // 4 warp-cols x 32

    uint32_t axhi = sb + GX_HI + (uint32_t)(mwarp + (lane & 15)) * GSTR + (lane >> 4) * 16;
    uint32_t axlo = axhi + (GX_LO - GX_HI);
    uint32_t bwhi = sb + GW_HI +
        (uint32_t)(nwarp + (lane & 7) + ((lane >> 4) & 1) * 8) * GSTR +
        ((lane >> 3) & 1) * 16;
    uint32_t bwlo = bwhi + (GW_LO - GW_HI);

    float acc[4][4][4];
    #pragma unroll
    for (int mi = 0; mi < 4; mi++)
        #pragma unroll
        for (int n8 = 0; n8 < 4; n8++)
            #pragma unroll
            for (int x = 0; x < 4; x++) acc[mi][n8][x] = 0.f;

    #pragma unroll
    for (int kk = 0; kk < 8; kk++) {
        uint32_t ah[4][4], al[4][4];
        #pragma unroll
        for (int mi = 0; mi < 4; mi++) {
            ldsm_x4(ah[mi], axhi + mi * 16 * GSTR + kk * 32);
            ldsm_x4(al[mi], axlo + mi * 16 * GSTR + kk * 32);
        }
        #pragma unroll
        for (int nb = 0; nb < 2; nb++) {
            uint32_t bh[4], bl[4];
            ldsm_x4(bh, bwhi + nb * 16 * GSTR + kk * 32);
            ldsm_x4(bl, bwlo + nb * 16 * GSTR + kk * 32);
            #pragma unroll
            for (int mi = 0; mi < 4; mi++) {
                mma16816(acc[mi][nb * 2 + 0], ah[mi], bh + 0);
                mma16816(acc[mi][nb * 2 + 1], ah[mi], bh + 2);
                mma16816(acc[mi][nb * 2 + 0], al[mi], bh + 0);
                mma16816(acc[mi][nb * 2 + 1], al[mi], bh + 2);
                mma16816(acc[mi][nb * 2 + 0], ah[mi], bl + 0);
                mma16816(acc[mi][nb * 2 + 1], ah[mi], bl + 2);
            }
        }
    }

    // epilogue
    #pragma unroll
    for (int mi = 0; mi < 4; mi++) {
        int r0 = mwarp + mi * 16 + (lane >> 2);
        #pragma unroll
        for (int n8 = 0; n8 < 4; n8++) {
            int col = nwarp + n8 * 8 + (lane & 3) * 2;
            float b0 = 0.f, b1 = 0.f;
            if (bias) { b0 = __ldg(bias + col); b1 = __ldg(bias + col + 1); }
            float v00 = acc[mi][n8][0] + b0, v01 = acc[mi][n8][1] + b1;
            float v10 = acc[mi][n8][2] + b0, v11 = acc[mi][n8][3] + b1;
            if (outh) {
                __half2 o0 = __floats2half2_rn(v00, v01);
                __half2 o1 = __floats2half2_rn(v10, v11);
                *(uint32_t*)(outh + (size_t)(i0 + r0) * FF + col) = h2u(o0);
                *(uint32_t*)(outh + (size_t)(i0 + r0 + 8) * FF + col) = h2u(o1);
            } else {
                *(float2*)(outf + (size_t)(i0 + r0) * FF + col) =
                    make_float2(leaky(v00), leaky(v01));
                *(float2*)(outf + (size_t)(i0 + r0 + 8) * FF + col) =
                    make_float2(leaky(v10), leaky(v11));
            }
        }
    }
}

// ---------------- kernel 4: dual-pipeline masked softmax-agg ----------------
#define PSTRIDE 144
#define PBUF 18432
#define VSTRIDE 272
#define VBUF 17408
#define PH_BASE 0
#define VH_BASE 73728
#define E2_OFF  143360
#define RS_OFF  176128
#define IV_OFF  178176
#define SM_TOTAL 178688
#define MRG_STRIDE 132

__global__ void __launch_bounds__(512, 1)
k_attn_mma() {
    extern __shared__ char sm[];
    int t = threadIdx.x;
    int lane = t & 31, wid = t >> 5;
    int g = wid >> 3;
    int w8 = wid & 7;
    int t256 = t & 255;
    int b = blockIdx.y;
    int it0 = blockIdx.x * 128;

    int mwarp = (w8 >> 2) * 64;
    int nwarp = (w8 & 3) * 32;

    uint32_t sbase = smem_u32(sm);
    uint32_t pgbase = sbase + PH_BASE + g * 2 * PBUF;
    uint32_t vgbase = sbase + VH_BASE + g * 2 * VBUF;
    uint32_t aoff = pgbase + (uint32_t)(mwarp + (lane & 15)) * PSTRIDE + (lane >> 4) * 16;
    uint32_t boff = vgbase + (uint32_t)(lane & 15) * VSTRIDE + (nwarp + (lane >> 4) * 8) * 2;

    int prow = t256 >> 1;
    int jh = (t256 & 1) * 32;
    float2 e1 = g_e1[b * NN + it0 + prow];
    float ea = e1.x, ea2 = e1.y;
    const uint32_t* maskp = g_adjbits + (size_t)(b * NN + it0 + prow) * (NN / 32) + (t256 & 1);
    const __half* vph = g_vph + (size_t)b * NN * FF;
    char* pdstH = sm + PH_BASE + g * 2 * PBUF + prow * PSTRIDE + jh * 2;
    const float4* e2q = (const float4*)(sm + E2_OFF) + (t256 & 1) * 16;

    int vr = t256 >> 2, vs = t256 & 3;
    uint32_t vdst = vgbase + vr * VSTRIDE + vs * 64;
    const __half* vsrc0 = vph + (size_t)vr * FF + vs * 32;

    {
        float4* d = (float4*)(sm + E2_OFF);
        const float4* s = (const float4*)(g_e2 + b * NN);
        #pragma unroll
        for (int kk = 0; kk < 4; kk++) d[t + kk * 512] = s[t + kk * 512];
    }

    float acc[4][4][4];
    #pragma unroll
    for (int mi = 0; mi < 4; mi++)
        #pragma unroll
        for (int n8 = 0; n8 < 4; n8++)
            #pragma unroll
            for (int x = 0; x < 4; x++) acc[mi][n8][x] = 0.f;
    float rs = 0.f;

    uint2 hiR[8];

    auto genP = [&](int c, uint32_t mask) {
        #pragma unroll
        for (int qq = 0; qq < 8; qq++) {
            float4 A  = e2q[c * 32 + qq * 2];
            float4 Bq = e2q[c * 32 + qq * 2 + 1];
            float p0 = (mask >> (qq * 4 + 0)) & 1u ? fmaxf(ea * A.x,  ea2 * A.y)  : 0.f;
            float p1 = (mask >> (qq * 4 + 1)) & 1u ? fmaxf(ea * A.z,  ea2 * A.w)  : 0.f;
            float p2 = (mask >> (qq * 4 + 2)) & 1u ? fmaxf(ea * Bq.x, ea2 * Bq.y) : 0.f;
            float p3 = (mask >> (qq * 4 + 3)) & 1u ? fmaxf(ea * Bq.z, ea2 * Bq.w) : 0.f;
            rs += (p0 + p1) + (p2 + p3);
            __half2 h01 = __floats2half2_rn(p0, p1);
            __half2 h23 = __floats2half2_rn(p2, p3);
            hiR[qq] = make_uint2(h2u(h01), h2u(h23));
        }
    };
    auto storeP = [&](int buf) {
        char* dh = pdstH + buf * PBUF;
        #pragma unroll
        for (int qq = 0; qq < 8; qq++)
            *(uint2*)(dh + qq * 8) = hiR[qq];
    };
    auto loadV = [&](int buf, int j0) {
        const __half* s = vsrc0 + (size_t)j0 * FF;
        uint32_t d = vdst + buf * VBUF;
        #pragma unroll
        for (int kk = 0; kk < 4; kk++)
            cp16(d + kk * 16, s + kk * 8);
        CP_COMMIT();
    };

    uint32_t mA = __ldg(maskp + 2 * g);
    uint32_t mB = __ldg(maskp + 2 * (g + 2));
    loadV(0, g * KC);
    __syncthreads();
    genP(g, mA);
    storeP(0);
    CP_WAIT0();
    BAR_G(g + 1);

    const int NIT = NN / KC / 2;
    for (int i = 0; i < NIT; i++) {
        int c = 2 * i + g;
        int buf = i & 1, nbuf = buf ^ 1;
        bool has_next = (i + 1) < NIT;
        uint32_t mC = 0;
        if (i + 2 < NIT) mC = __ldg(maskp + 2 * (c + 4));
        if (has_next) {
            loadV(nbuf, (c + 2) * KC);
            genP(c + 2, mB);
        }
        uint32_t pb = aoff + buf * PBUF;
        uint32_t vb = boff + buf * VBUF;
        #pragma unroll
        for (int kk = 0; kk < 4; kk++) {
            uint32_t ah[4][4];
            #pragma unroll
            for (int mi = 0; mi < 4; mi++)
                ldsm_x4(ah[mi], pb + mi * 16 * PSTRIDE + kk * 32);
            #pragma unroll
            for (int nb = 0; nb < 2; nb++) {
                uint32_t bh[4];
                ldsm_x4_t(bh, vb + kk * 16 * VSTRIDE + nb * 32);
                #pragma unroll
                for (int mi = 0; mi < 4; mi++) {
                    mma16816(acc[mi][nb * 2 + 0], ah[mi], bh + 0);
                    mma16816(acc[mi][nb * 2 + 1], ah[mi], bh + 2);
                }
            }
        }
        if (has_next) storeP(nbuf);
        mB = mC;
        CP_WAIT0();
        BAR_G(g + 1);
    }

    ((float*)(sm + RS_OFF))[g * 256 + t256] = rs;
    __syncthreads();

    float* mbuf = (float*)sm;
    if (g == 1) {
        #pragma unroll
        for (int mi = 0; mi < 4; mi++) {
            int r0 = mwarp + mi * 16 + (lane >> 2);
            #pragma unroll
            for (int n8 = 0; n8 < 4; n8++) {
                int col = nwarp + n8 * 8 + (lane & 3) * 2;
                *(float2*)&mbuf[r0 * MRG_STRIDE + col] =
                    make_float2(acc[mi][n8][0], acc[mi][n8][1]);
                *(float2*)&mbuf[(r0 + 8) * MRG_STRIDE + col] =
                    make_float2(acc[mi][n8][2], acc[mi][n8][3]);
            }
        }
    } else if (t < 128) {
        const float* rss = (const float*)(sm + RS_OFF);
        float s = (rss[2 * t] + rss[2 * t + 1]) + (rss[256 + 2 * t] + rss[256 + 2 * t + 1]);
        ((float*)(sm + IV_OFF))[t] = 1.0f / s;
    }
    __syncthreads();

    if (g == 0) {
        const float* inv = (const float*)(sm + IV_OFF);
        #pragma unroll
        for (int mi = 0; mi < 4; mi++) {
            int r0 = mwarp + mi * 16 + (lane >> 2);
            float iv0 = inv[r0], iv1 = inv[r0 + 8];
            #pragma unroll
            for (int n8 = 0; n8 < 4; n8++) {
                int col = nwarp + n8 * 8 + (lane & 3) * 2;
                float2 m0 = *(const float2*)&mbuf[r0 * MRG_STRIDE + col];
                float2 m1 = *(const float2*)&mbuf[(r0 + 8) * MRG_STRIDE + col];
                float2 v0 = make_float2((acc[mi][n8][0] + m0.x) * iv0,
                                        (acc[mi][n8][1] + m0.y) * iv0);
                float2 v1 = make_float2((acc[mi][n8][2] + m1.x) * iv1,
                                        (acc[mi][n8][3] + m1.y) * iv1);
                *(float2*)(g_h + (size_t)(b * NN + it0 + r0) * FF + col) = v0;
                *(float2*)(g_h + (size_t)(b * NN + it0 + r0 + 8) * FF + col) = v1;
            }
        }
    }
}

// ---------------- launch ----------------
extern "C" void kernel_launch(void* const* d_in, const int* in_sizes, int n_in,
                              void* d_out, int out_size) {
    const float* q    = (const float*)d_in[0];
    const float* k    = (const float*)d_in[1];
    const float* v    = (const float*)d_in[2];
    const int*   adj  = (const int*)  d_in[3];
    const float* Wq_w = (const float*)d_in[4];
    const float* Wq_b = (const float*)d_in[5];
    const float* Wk_w = (const float*)d_in[6];
    const float* Wk_b = (const float*)d_in[7];
    const float* Wv_w = (const float*)d_in[8];
    const float* Wv_b = (const float*)d_in[9];
    const float* a    = (const float*)d_in[10];
    const float* Wo_w = (const float*)d_in[11];
    float* out = (float*)d_out;

    void* h_ptr = nullptr;
    cudaGetSymbolAddress(&h_ptr, g_h);
    void* vph_ptr = nullptr;
    cudaGetSymbolAddress(&vph_ptr, g_vph);

    cudaFuncSetAttribute(k_attn_mma, cudaFuncAttributeMaxDynamicSharedMemorySize, SM_TOTAL);
    cudaFuncSetAttribute(k_gemm_tc, cudaFuncAttributeMaxDynamicSharedMemorySize, G_TOTAL);

    k_pack<<<(BB * NN * NN) / (256 * 8), 256>>>(adj);
    k_prep<<<1, 128>>>(Wq_w, Wq_b, Wk_w, Wk_b, a);
    k_wh<<<(2 * BB * NN) / 8, 256>>>(q, k);
    k_gemm_tc<<<BB * NN / 128, 256, G_TOTAL>>>(v, Wv_w, Wv_b, nullptr, (__half*)vph_ptr);
    {
        dim3 grid(NN / 128, BB);
        k_attn_mma<<<grid, 512, SM_TOTAL>>>();
    }
    k_gemm_tc<<<BB * NN / 128, 256, G_TOTAL>>>((const float*)h_ptr, Wo_w, nullptr, out, nullptr);
}

// round 12
// speedup vs baseline: 1.4650x; 1.0027x over previous
#include <cuda_runtime.h>
#include <cuda_fp16.h>
#include <cstdint>

#define BB 4
#define NN 4096
#define FF 128
#define ALPHA 0.1f
#define KC 64

// ---------------- device scratch ----------------
__device__ float g_w1[FF], g_w2[FF], g_c[2];
__device__ __align__(16) float2 g_e1[BB * NN];   // (exp(wh1), exp(0.1*wh1))
__device__ __align__(16) float2 g_e2[BB * NN];   // (exp(wh2), exp(0.1*wh2))
__device__ float g_h[BB * NN * FF];                             // 8 MB
__device__ __align__(16) __half g_vph[BB * NN * FF];            // 4 MB fp16 [b][j][f]
__device__ __align__(16) uint32_t g_adjbits[BB * NN * (NN/32)]; // 8.4 MB bitmask

__device__ __forceinline__ float leaky(float x) { return fmaxf(x, ALPHA * x); }

// ---------------- mma.sync helpers ----------------
__device__ __forceinline__ void mma16816(float* d, const uint32_t* a, const uint32_t* b) {
    asm volatile("mma.sync.aligned.m16n8k16.row.col.f32.f16.f16.f32 "
        "{%0,%1,%2,%3},{%4,%5,%6,%7},{%8,%9},{%0,%1,%2,%3};"
        : "+f"(d[0]), "+f"(d[1]), "+f"(d[2]), "+f"(d[3])
        : "r"(a[0]), "r"(a[1]), "r"(a[2]), "r"(a[3]), "r"(b[0]), "r"(b[1]));
}
__device__ __forceinline__ void ldsm_x4(uint32_t* r, uint32_t addr) {
    asm volatile("ldmatrix.sync.aligned.m8n8.x4.shared.b16 {%0,%1,%2,%3},[%4];"
        : "=r"(r[0]), "=r"(r[1]), "=r"(r[2]), "=r"(r[3]) : "r"(addr));
}
__device__ __forceinline__ void ldsm_x4_t(uint32_t* r, uint32_t addr) {
    asm volatile("ldmatrix.sync.aligned.m8n8.x4.trans.shared.b16 {%0,%1,%2,%3},[%4];"
        : "=r"(r[0]), "=r"(r[1]), "=r"(r[2]), "=r"(r[3]) : "r"(addr));
}
__device__ __forceinline__ uint32_t smem_u32(const void* p) {
    uint32_t a;
    asm("{ .reg .u64 t; cvta.to.shared.u64 t, %1; cvt.u32.u64 %0, t; }" : "=r"(a) : "l"(p));
    return a;
}
__device__ __forceinline__ void cp16(uint32_t dst, const void* src) {
    asm volatile("cp.async.cg.shared.global [%0], [%1], 16;" :: "r"(dst), "l"(src) : "memory");
}
#define CP_COMMIT() asm volatile("cp.async.commit_group;" ::: "memory")
#define CP_WAIT0()  asm volatile("cp.async.wait_group 0;" ::: "memory")
#define BAR_G(id)   asm volatile("bar.sync %0, 256;" :: "r"(id) : "memory")
__device__ __forceinline__ uint32_t h2u(__half2 h) { return *(uint32_t*)&h; }

// ---------------- kernel 0: pack adj into bitmask (vectorized) -------------
__global__ void __launch_bounds__(256) k_pack(const int* __restrict__ adj) {
    int t = blockIdx.x * 256 + threadIdx.x;
    const int4* p = (const int4*)adj + (size_t)t * 2;
    int4 a = p[0], b = p[1];
    uint32_t bits =
        (uint32_t)(a.x != 0)        | ((uint32_t)(a.y != 0) << 1) |
        ((uint32_t)(a.z != 0) << 2) | ((uint32_t)(a.w != 0) << 3) |
        ((uint32_t)(b.x != 0) << 4) | ((uint32_t)(b.y != 0) << 5) |
        ((uint32_t)(b.z != 0) << 6) | ((uint32_t)(b.w != 0) << 7);
    int lane = threadIdx.x & 31;
    uint32_t my = bits << ((lane & 3) * 8);
    my |= __shfl_xor_sync(0xffffffffu, my, 1);
    my |= __shfl_xor_sync(0xffffffffu, my, 2);
    if ((lane & 3) == 0) g_adjbits[t >> 2] = my;
}

// ---------------- kernel 1: fold a into Q/K projections ----------------
__global__ void k_prep(const float* __restrict__ Wq_w, const float* __restrict__ Wq_b,
                       const float* __restrict__ Wk_w, const float* __restrict__ Wk_b,
                       const float* __restrict__ a) {
    int f = threadIdx.x;
    float s1 = 0.f, s2 = 0.f;
    for (int o = 0; o < FF; o++) {
        s1 += Wq_w[o * FF + f] * a[o];
        s2 += Wk_w[o * FF + f] * a[FF + o];
    }
    g_w1[f] = s1; g_w2[f] = s2;
    if (f == 0) {
        float c1 = 0.f, c2 = 0.f;
        for (int o = 0; o < FF; o++) { c1 += Wq_b[o] * a[o]; c2 += Wk_b[o] * a[FF + o]; }
        g_c[0] = c1; g_c[1] = c2;
    }
}

// ---------------- kernel 2: Wh -> (exp(wh), exp(0.1 wh)) pairs -------------
__global__ void k_wh(const float* __restrict__ q, const float* __restrict__ k) {
    int warp = threadIdx.x >> 5, lane = threadIdx.x & 31;
    int row = blockIdx.x * 8 + warp;
    const float* src; const float* w; float c; float2* dst; int r;
    if (row < BB * NN) { src = q; w = g_w1; c = g_c[0]; dst = g_e1; r = row; }
    else               { src = k; w = g_w2; c = g_c[1]; dst = g_e2; r = row - BB * NN; }
    float4 x  = ((const float4*)(src + (size_t)r * FF))[lane];
    float4 ww = ((const float4*)w)[lane];
    float s = x.x * ww.x + x.y * ww.y + x.z * ww.z + x.w * ww.w;
    #pragma unroll
    for (int o = 16; o > 0; o >>= 1) s += __shfl_xor_sync(0xffffffffu, s, o);
    if (lane == 0) {
        float wh = s + c;
        dst[r] = make_float2(__expf(wh), __expf(ALPHA * wh));
    }
}

// ---------------- kernel 3/5: tensor-core projection GEMM (64-row CTAs) ----
#define GSTR 272             // bytes per smem row (136 halves)
#define GX_HI 0              // 64 rows:  17408
#define GX_LO 17408
#define GW_HI 34816          // 128 rows: 34816
#define GW_LO 69632
#define G_TOTAL 104448

__global__ void __launch_bounds__(256, 2)
k_gemm_tc(const float* __restrict__ in, const float* __restrict__ W,
          const float* __restrict__ bias, float* __restrict__ outf,
          __half* __restrict__ outh) {
    extern __shared__ char sm[];
    int t = threadIdx.x, lane = t & 31, wid = t >> 5;
    int i0 = blockIdx.x * 64;
    uint32_t sb = smem_u32(sm);

    // convert X (64 rows) to fp16 hi/lo
    #pragma unroll
    for (int kk = 0; kk < 8; kk++) {
        int e = t + kk * 256;
        int row = e >> 5, f4 = e & 31;
        int off = row * GSTR + f4 * 8;
        float4 xv = *(const float4*)(in + (size_t)(i0 + row) * FF + f4 * 4);
        __half2 xh01 = __floats2half2_rn(xv.x, xv.y);
        __half2 xh23 = __floats2half2_rn(xv.z, xv.w);
        float2 xf01 = __half22float2(xh01), xf23 = __half22float2(xh23);
        __half2 xl01 = __floats2half2_rn(xv.x - xf01.x, xv.y - xf01.y);
        __half2 xl23 = __floats2half2_rn(xv.z - xf23.x, xv.w - xf23.y);
        *(uint2*)(sm + GX_HI + off) = make_uint2(h2u(xh01), h2u(xh23));
        *(uint2*)(sm + GX_LO + off) = make_uint2(h2u(xl01), h2u(xl23));
    }
    // convert W (128 rows) to fp16 hi/lo
    #pragma unroll
    for (int kk = 0; kk < 16; kk++) {
        int e = t + kk * 256;
        int row = e >> 5, f4 = e & 31;
        int off = row * GSTR + f4 * 8;
        float4 wv = *(const float4*)(W + (size_t)row * FF + f4 * 4);
        __half2 wh01 = __floats2half2_rn(wv.x, wv.y);
        __half2 wh23 = __floats2half2_rn(wv.z, wv.w);
        float2 wf01 = __half22float2(wh01), wf23 = __half22float2(wh23);
        __half2 wl01 = __floats2half2_rn(wv.x - wf01.x, wv.y - wf01.y);
        __half2 wl23 = __floats2half2_rn(wv.z - wf23.x, wv.w - wf23.y);
        *(uint2*)(sm + GW_HI + off) = make_uint2(h2u(wh01), h2u(wh23));
        *(uint2*)(sm + GW_LO + off) = make_uint2(h2u(wl01), h2u(wl23));
    }
    __syncthreads();

    int mwarp = (wid >> 2) * 32;     // 2 warp-rows x 32
    int nwarp = (wid & 3) * 32;      // 4 warp-cols x 32

    uint32_t axhi = sb + GX_HI + (uint32_t)(mwarp + (lane & 15)) * GSTR + (lane >> 4) * 16;
    uint32_t axlo = axhi + (GX_LO - GX_HI);
    uint32_t bwhi = sb + GW_HI +
        (uint32_t)(nwarp + (lane & 7) + ((lane >> 4) & 1) * 8) * GSTR +
        ((lane >> 3) & 1) * 16;
    uint32_t bwlo = bwhi + (GW_LO - GW_HI);

    float acc[2][4][4];
    #pragma unroll
    for (int mi = 0; mi < 2; mi++)
        #pragma unroll
        for (int n8 = 0; n8 < 4; n8++)
            #pragma unroll
            for (int x = 0; x < 4; x++) acc[mi][n8][x] = 0.f;

    #pragma unroll
    for (int kk = 0; kk < 8; kk++) {
        uint32_t ah[2][4], al[2][4];
        #pragma unroll
        for (int mi = 0; mi < 2; mi++) {
            ldsm_x4(ah[mi], axhi + mi * 16 * GSTR + kk * 32);
            ldsm_x4(al[mi], axlo + mi * 16 * GSTR + kk * 32);
        }
        #pragma unroll
        for (int nb = 0; nb < 2; nb++) {
            uint32_t bh[4], bl[4];
            ldsm_x4(bh, bwhi + nb * 16 * GSTR + kk * 32);
            ldsm_x4(bl, bwlo + nb * 16 * GSTR + kk * 32);
            #pragma unroll
            for (int mi = 0; mi < 2; mi++) {
                mma16816(acc[mi][nb * 2 + 0], ah[mi], bh + 0);
                mma16816(acc[mi][nb * 2 + 1], ah[mi], bh + 2);
                mma16816(acc[mi][nb * 2 + 0], al[mi], bh + 0);
                mma16816(acc[mi][nb * 2 + 1], al[mi], bh + 2);
                mma16816(acc[mi][nb * 2 + 0], ah[mi], bl + 0);
                mma16816(acc[mi][nb * 2 + 1], ah[mi], bl + 2);
            }
        }
    }

    // epilogue
    #pragma unroll
    for (int mi = 0; mi < 2; mi++) {
        int r0 = mwarp + mi * 16 + (lane >> 2);
        #pragma unroll
        for (int n8 = 0; n8 < 4; n8++) {
            int col = nwarp + n8 * 8 + (lane & 3) * 2;
            float b0 = 0.f, b1 = 0.f;
            if (bias) { b0 = __ldg(bias + col); b1 = __ldg(bias + col + 1); }
            float v00 = acc[mi][n8][0] + b0, v01 = acc[mi][n8][1] + b1;
            float v10 = acc[mi][n8][2] + b0, v11 = acc[mi][n8][3] + b1;
            if (outh) {
                __half2 o0 = __floats2half2_rn(v00, v01);
                __half2 o1 = __floats2half2_rn(v10, v11);
                *(uint32_t*)(outh + (size_t)(i0 + r0) * FF + col) = h2u(o0);
                *(uint32_t*)(outh + (size_t)(i0 + r0 + 8) * FF + col) = h2u(o1);
            } else {
                *(float2*)(outf + (size_t)(i0 + r0) * FF + col) =
                    make_float2(leaky(v00), leaky(v01));
                *(float2*)(outf + (size_t)(i0 + r0 + 8) * FF + col) =
                    make_float2(leaky(v10), leaky(v11));
            }
        }
    }
}

// ---------------- kernel 4: dual-pipeline masked softmax-agg ----------------
#define PSTRIDE 144
#define PBUF 18432
#define VSTRIDE 272
#define VBUF 17408
#define PH_BASE 0
#define VH_BASE 73728
#define E2_OFF  143360
#define RS_OFF  176128
#define IV_OFF  178176
#define SM_TOTAL 178688
#define MRG_STRIDE 132

__global__ void __launch_bounds__(512, 1)
k_attn_mma() {
    extern __shared__ char sm[];
    int t = threadIdx.x;
    int lane = t & 31, wid = t >> 5;
    int g = wid >> 3;
    int w8 = wid & 7;
    int t256 = t & 255;
    int b = blockIdx.y;
    int it0 = blockIdx.x * 128;

    int mwarp = (w8 >> 2) * 64;
    int nwarp = (w8 & 3) * 32;

    uint32_t sbase = smem_u32(sm);
    uint32_t pgbase = sbase + PH_BASE + g * 2 * PBUF;
    uint32_t vgbase = sbase + VH_BASE + g * 2 * VBUF;
    uint32_t aoff = pgbase + (uint32_t)(mwarp + (lane & 15)) * PSTRIDE + (lane >> 4) * 16;
    uint32_t boff = vgbase + (uint32_t)(lane & 15) * VSTRIDE + (nwarp + (lane >> 4) * 8) * 2;

    int prow = t256 >> 1;
    int jh = (t256 & 1) * 32;
    float2 e1 = g_e1[b * NN + it0 + prow];
    float ea = e1.x, ea2 = e1.y;
    const uint32_t* maskp = g_adjbits + (size_t)(b * NN + it0 + prow) * (NN / 32) + (t256 & 1);
    const __half* vph = g_vph + (size_t)b * NN * FF;
    char* pdstH = sm + PH_BASE + g * 2 * PBUF + prow * PSTRIDE + jh * 2;
    const float4* e2q = (const float4*)(sm + E2_OFF) + (t256 & 1) * 16;

    int vr = t256 >> 2, vs = t256 & 3;
    uint32_t vdst = vgbase + vr * VSTRIDE + vs * 64;
    const __half* vsrc0 = vph + (size_t)vr * FF + vs * 32;

    {
        float4* d = (float4*)(sm + E2_OFF);
        const float4* s = (const float4*)(g_e2 + b * NN);
        #pragma unroll
        for (int kk = 0; kk < 4; kk++) d[t + kk * 512] = s[t + kk * 512];
    }

    float acc[4][4][4];
    #pragma unroll
    for (int mi = 0; mi < 4; mi++)
        #pragma unroll
        for (int n8 = 0; n8 < 4; n8++)
            #pragma unroll
            for (int x = 0; x < 4; x++) acc[mi][n8][x] = 0.f;
    float rs = 0.f;

    uint2 hiR[8];

    auto genP = [&](int c, uint32_t mask) {
        #pragma unroll
        for (int qq = 0; qq < 8; qq++) {
            float4 A  = e2q[c * 32 + qq * 2];
            float4 Bq = e2q[c * 32 + qq * 2 + 1];
            float p0 = (mask >> (qq * 4 + 0)) & 1u ? fmaxf(ea * A.x,  ea2 * A.y)  : 0.f;
            float p1 = (mask >> (qq * 4 + 1)) & 1u ? fmaxf(ea * A.z,  ea2 * A.w)  : 0.f;
            float p2 = (mask >> (qq * 4 + 2)) & 1u ? fmaxf(ea * Bq.x, ea2 * Bq.y) : 0.f;
            float p3 = (mask >> (qq * 4 + 3)) & 1u ? fmaxf(ea * Bq.z, ea2 * Bq.w) : 0.f;
            rs += (p0 + p1) + (p2 + p3);
            __half2 h01 = __floats2half2_rn(p0, p1);
            __half2 h23 = __floats2half2_rn(p2, p3);
            hiR[qq] = make_uint2(h2u(h01), h2u(h23));
        }
    };
    auto storeP = [&](int buf) {
        char* dh = pdstH + buf * PBUF;
        #pragma unroll
        for (int qq = 0; qq < 8; qq++)
            *(uint2*)(dh + qq * 8) = hiR[qq];
    };
    auto loadV = [&](int buf, int j0) {
        const __half* s = vsrc0 + (size_t)j0 * FF;
        uint32_t d = vdst + buf * VBUF;
        #pragma unroll
        for (int kk = 0; kk < 4; kk++)
            cp16(d + kk * 16, s + kk * 8);
        CP_COMMIT();
    };

    uint32_t mA = __ldg(maskp + 2 * g);
    uint32_t mB = __ldg(maskp + 2 * (g + 2));
    loadV(0, g * KC);
    __syncthreads();
    genP(g, mA);
    storeP(0);
    CP_WAIT0();
    BAR_G(g + 1);

    const int NIT = NN / KC / 2;
    for (int i = 0; i < NIT; i++) {
        int c = 2 * i + g;
        int buf = i & 1, nbuf = buf ^ 1;
        bool has_next = (i + 1) < NIT;
        uint32_t mC = 0;
        if (i + 2 < NIT) mC = __ldg(maskp + 2 * (c + 4));
        if (has_next) {
            loadV(nbuf, (c + 2) * KC);
            genP(c + 2, mB);
        }
        uint32_t pb = aoff + buf * PBUF;
        uint32_t vb = boff + buf * VBUF;
        #pragma unroll
        for (int kk = 0; kk < 4; kk++) {
            uint32_t ah[4][4];
            #pragma unroll
            for (int mi = 0; mi < 4; mi++)
                ldsm_x4(ah[mi], pb + mi * 16 * PSTRIDE + kk * 32);
            #pragma unroll
            for (int nb = 0; nb < 2; nb++) {
                uint32_t bh[4];
                ldsm_x4_t(bh, vb + kk * 16 * VSTRIDE + nb * 32);
                #pragma unroll
                for (int mi = 0; mi < 4; mi++) {
                    mma16816(acc[mi][nb * 2 + 0], ah[mi], bh + 0);
                    mma16816(acc[mi][nb * 2 + 1], ah[mi], bh + 2);
                }
            }
        }
        if (has_next) storeP(nbuf);
        mB = mC;
        CP_WAIT0();
        BAR_G(g + 1);
    }

    ((float*)(sm + RS_OFF))[g * 256 + t256] = rs;
    __syncthreads();

    float* mbuf = (float*)sm;
    if (g == 1) {
        #pragma unroll
        for (int mi = 0; mi < 4; mi++) {
            int r0 = mwarp + mi * 16 + (lane >> 2);
            #pragma unroll
            for (int n8 = 0; n8 < 4; n8++) {
                int col = nwarp + n8 * 8 + (lane & 3) * 2;
                *(float2*)&mbuf[r0 * MRG_STRIDE + col] =
                    make_float2(acc[mi][n8][0], acc[mi][n8][1]);
                *(float2*)&mbuf[(r0 + 8) * MRG_STRIDE + col] =
                    make_float2(acc[mi][n8][2], acc[mi][n8][3]);
            }
        }
    } else if (t < 128) {
        const float* rss = (const float*)(sm + RS_OFF);
        float s = (rss[2 * t] + rss[2 * t + 1]) + (rss[256 + 2 * t] + rss[256 + 2 * t + 1]);
        ((float*)(sm + IV_OFF))[t] = 1.0f / s;
    }
    __syncthreads();

    if (g == 0) {
        const float* inv = (const float*)(sm + IV_OFF);
        #pragma unroll
        for (int mi = 0; mi < 4; mi++) {
            int r0 = mwarp + mi * 16 + (lane >> 2);
            float iv0 = inv[r0], iv1 = inv[r0 + 8];
            #pragma unroll
            for (int n8 = 0; n8 < 4; n8++) {
                int col = nwarp + n8 * 8 + (lane & 3) * 2;
                float2 m0 = *(const float2*)&mbuf[r0 * MRG_STRIDE + col];
                float2 m1 = *(const float2*)&mbuf[(r0 + 8) * MRG_STRIDE + col];
                float2 v0 = make_float2((acc[mi][n8][0] + m0.x) * iv0,
                                        (acc[mi][n8][1] + m0.y) * iv0);
                float2 v1 = make_float2((acc[mi][n8][2] + m1.x) * iv1,
                                        (acc[mi][n8][3] + m1.y) * iv1);
                *(float2*)(g_h + (size_t)(b * NN + it0 + r0) * FF + col) = v0;
                *(float2*)(g_h + (size_t)(b * NN + it0 + r0 + 8) * FF + col) = v1;
            }
        }
    }
}

// ---------------- launch ----------------
extern "C" void kernel_launch(void* const* d_in, const int* in_sizes, int n_in,
                              void* d_out, int out_size) {
    const float* q    = (const float*)d_in[0];
    const float* k    = (const float*)d_in[1];
    const float* v    = (const float*)d_in[2];
    const int*   adj  = (const int*)  d_in[3];
    const float* Wq_w = (const float*)d_in[4];
    const float* Wq_b = (const float*)d_in[5];
    const float* Wk_w = (const float*)d_in[6];
    const float* Wk_b = (const float*)d_in[7];
    const float* Wv_w = (const float*)d_in[8];
    const float* Wv_b = (const float*)d_in[9];
    const float* a    = (const float*)d_in[10];
    const float* Wo_w = (const float*)d_in[11];
    float* out = (float*)d_out;

    void* h_ptr = nullptr;
    cudaGetSymbolAddress(&h_ptr, g_h);
    void* vph_ptr = nullptr;
    cudaGetSymbolAddress(&vph_ptr, g_vph);

    static cudaStream_t s1 = nullptr;
    static cudaEvent_t evFork = nullptr, evJoin = nullptr;
    if (!s1) {
        cudaStreamCreateWithFlags(&s1, cudaStreamNonBlocking);
        cudaEventCreateWithFlags(&evFork, cudaEventDisableTiming);
        cudaEventCreateWithFlags(&evJoin, cudaEventDisableTiming);
    }

    cudaFuncSetAttribute(k_attn_mma, cudaFuncAttributeMaxDynamicSharedMemorySize, SM_TOTAL);
    cudaFuncSetAttribute(k_gemm_tc, cudaFuncAttributeMaxDynamicSharedMemorySize, G_TOTAL);

    // fork: pack on s1, projections on main stream
    cudaEventRecord(evFork, 0);
    cudaStreamWaitEvent(s1, evFork, 0);
    k_pack<<<(BB * NN * NN) / (256 * 8), 256, 0, s1>>>(adj);

    k_prep<<<1, 128>>>(Wq_w, Wq_b, Wk_w, Wk_b, a);
    k_wh<<<(2 * BB * NN) / 8, 256>>>(q, k);
    k_gemm_tc<<<BB * NN / 64, 256, G_TOTAL>>>(v, Wv_w, Wv_b, nullptr, (__half*)vph_ptr);

    // join before attn
    cudaEventRecord(evJoin, s1);
    cudaStreamWaitEvent(0, evJoin, 0);

    {
        dim3 grid(NN / 128, BB);
        k_attn_mma<<<grid, 512, SM_TOTAL>>>();
    }
    k_gemm_tc<<<BB * NN / 64, 256, G_TOTAL>>>((const float*)h_ptr, Wo_w, nullptr, out, nullptr);
}

// round 13
// speedup vs baseline: 1.4753x; 1.0071x over previous
#include <cuda_runtime.h>
#include <cuda_fp16.h>
#include <cstdint>

#define BB 4
#define NN 4096
#define FF 128
#define ALPHA 0.1f
#define KC 64

// ---------------- device scratch ----------------
__device__ float g_w1[FF], g_w2[FF], g_c[2];
__device__ __align__(16) float2 g_e1[BB * NN];   // (exp(wh1), exp(0.1*wh1))
__device__ __align__(16) float2 g_e2[BB * NN];   // (exp(wh2), exp(0.1*wh2))
__device__ __align__(16) __half g_vph[BB * NN * FF];            // 4 MB fp16 [b][j][f]
__device__ __align__(16) __half g_woh[FF * FF];                 // Wo fp16 hi
__device__ __align__(16) __half g_wol[FF * FF];                 // Wo fp16 lo
__device__ __align__(16) uint32_t g_adjbits[BB * NN * (NN/32)]; // 8.4 MB bitmask

__device__ __forceinline__ float leaky(float x) { return fmaxf(x, ALPHA * x); }

// ---------------- mma.sync helpers ----------------
__device__ __forceinline__ void mma16816(float* d, const uint32_t* a, const uint32_t* b) {
    asm volatile("mma.sync.aligned.m16n8k16.row.col.f32.f16.f16.f32 "
        "{%0,%1,%2,%3},{%4,%5,%6,%7},{%8,%9},{%0,%1,%2,%3};"
        : "+f"(d[0]), "+f"(d[1]), "+f"(d[2]), "+f"(d[3])
        : "r"(a[0]), "r"(a[1]), "r"(a[2]), "r"(a[3]), "r"(b[0]), "r"(b[1]));
}
__device__ __forceinline__ void ldsm_x4(uint32_t* r, uint32_t addr) {
    asm volatile("ldmatrix.sync.aligned.m8n8.x4.shared.b16 {%0,%1,%2,%3},[%4];"
        : "=r"(r[0]), "=r"(r[1]), "=r"(r[2]), "=r"(r[3]) : "r"(addr));
}
__device__ __forceinline__ void ldsm_x4_t(uint32_t* r, uint32_t addr) {
    asm volatile("ldmatrix.sync.aligned.m8n8.x4.trans.shared.b16 {%0,%1,%2,%3},[%4];"
        : "=r"(r[0]), "=r"(r[1]), "=r"(r[2]), "=r"(r[3]) : "r"(addr));
}
__device__ __forceinline__ uint32_t smem_u32(const void* p) {
    uint32_t a;
    asm("{ .reg .u64 t; cvta.to.shared.u64 t, %1; cvt.u32.u64 %0, t; }" : "=r"(a) : "l"(p));
    return a;
}
__device__ __forceinline__ void cp16(uint32_t dst, const void* src) {
    asm volatile("cp.async.cg.shared.global [%0], [%1], 16;" :: "r"(dst), "l"(src) : "memory");
}
#define CP_COMMIT() asm volatile("cp.async.commit_group;" ::: "memory")
#define CP_WAIT0()  asm volatile("cp.async.wait_group 0;" ::: "memory")
#define BAR_G(id)   asm volatile("bar.sync %0, 256;" :: "r"(id) : "memory")
__device__ __forceinline__ uint32_t h2u(__half2 h) { return *(uint32_t*)&h; }

// ---------------- kernel 0: pack adj into bitmask ----------------
__global__ void __launch_bounds__(256) k_pack(const int* __restrict__ adj) {
    int t = blockIdx.x * 256 + threadIdx.x;
    const int4* p = (const int4*)adj + (size_t)t * 2;
    int4 a = p[0], b = p[1];
    uint32_t bits =
        (uint32_t)(a.x != 0)        | ((uint32_t)(a.y != 0) << 1) |
        ((uint32_t)(a.z != 0) << 2) | ((uint32_t)(a.w != 0) << 3) |
        ((uint32_t)(b.x != 0) << 4) | ((uint32_t)(b.y != 0) << 5) |
        ((uint32_t)(b.z != 0) << 6) | ((uint32_t)(b.w != 0) << 7);
    int lane = threadIdx.x & 31;
    uint32_t my = bits << ((lane & 3) * 8);
    my |= __shfl_xor_sync(0xffffffffu, my, 1);
    my |= __shfl_xor_sync(0xffffffffu, my, 2);
    if ((lane & 3) == 0) g_adjbits[t >> 2] = my;
}

// ---------------- kernel 1: fold a into Q/K projections ----------------
__global__ void k_prep(const float* __restrict__ Wq_w, const float* __restrict__ Wq_b,
                       const float* __restrict__ Wk_w, const float* __restrict__ Wk_b,
                       const float* __restrict__ a) {
    int f = threadIdx.x;
    float s1 = 0.f, s2 = 0.f;
    for (int o = 0; o < FF; o++) {
        s1 += Wq_w[o * FF + f] * a[o];
        s2 += Wk_w[o * FF + f] * a[FF + o];
    }
    g_w1[f] = s1; g_w2[f] = s2;
    if (f == 0) {
        float c1 = 0.f, c2 = 0.f;
        for (int o = 0; o < FF; o++) { c1 += Wq_b[o] * a[o]; c2 += Wk_b[o] * a[FF + o]; }
        g_c[0] = c1; g_c[1] = c2;
    }
}

// ---------------- kernel 2: Wh -> (exp(wh), exp(0.1 wh)) pairs -------------
__global__ void k_wh(const float* __restrict__ q, const float* __restrict__ k) {
    int warp = threadIdx.x >> 5, lane = threadIdx.x & 31;
    int row = blockIdx.x * 8 + warp;
    const float* src; const float* w; float c; float2* dst; int r;
    if (row < BB * NN) { src = q; w = g_w1; c = g_c[0]; dst = g_e1; r = row; }
    else               { src = k; w = g_w2; c = g_c[1]; dst = g_e2; r = row - BB * NN; }
    float4 x  = ((const float4*)(src + (size_t)r * FF))[lane];
    float4 ww = ((const float4*)w)[lane];
    float s = x.x * ww.x + x.y * ww.y + x.z * ww.z + x.w * ww.w;
    #pragma unroll
    for (int o = 16; o > 0; o >>= 1) s += __shfl_xor_sync(0xffffffffu, s, o);
    if (lane == 0) {
        float wh = s + c;
        dst[r] = make_float2(__expf(wh), __expf(ALPHA * wh));
    }
}

// ---------------- kernel 3: V projection, tensor core (128-row CTAs) -------
#define GSTR 272
#define GX_HI 0
#define GX_LO 34816
#define GW_HI 69632
#define GW_LO 104448
#define G_TOTAL 139264

__global__ void __launch_bounds__(256, 1)
k_gemm_tc(const float* __restrict__ in, const float* __restrict__ W,
          const float* __restrict__ bias, __half* __restrict__ outh) {
    extern __shared__ char sm[];
    int t = threadIdx.x, lane = t & 31, wid = t >> 5;
    int i0 = blockIdx.x * 128;
    uint32_t sb = smem_u32(sm);

    #pragma unroll
    for (int kk = 0; kk < 16; kk++) {
        int e = t + kk * 256;
        int row = e >> 5, f4 = e & 31;
        int off = row * GSTR + f4 * 8;
        float4 xv = *(const float4*)(in + (size_t)(i0 + row) * FF + f4 * 4);
        __half2 xh01 = __floats2half2_rn(xv.x, xv.y);
        __half2 xh23 = __floats2half2_rn(xv.z, xv.w);
        float2 xf01 = __half22float2(xh01), xf23 = __half22float2(xh23);
        __half2 xl01 = __floats2half2_rn(xv.x - xf01.x, xv.y - xf01.y);
        __half2 xl23 = __floats2half2_rn(xv.z - xf23.x, xv.w - xf23.y);
        *(uint2*)(sm + GX_HI + off) = make_uint2(h2u(xh01), h2u(xh23));
        *(uint2*)(sm + GX_LO + off) = make_uint2(h2u(xl01), h2u(xl23));
        float4 wv = *(const float4*)(W + (size_t)row * FF + f4 * 4);
        __half2 wh01 = __floats2half2_rn(wv.x, wv.y);
        __half2 wh23 = __floats2half2_rn(wv.z, wv.w);
        float2 wf01 = __half22float2(wh01), wf23 = __half22float2(wh23);
        __half2 wl01 = __floats2half2_rn(wv.x - wf01.x, wv.y - wf01.y);
        __half2 wl23 = __floats2half2_rn(wv.z - wf23.x, wv.w - wf23.y);
        *(uint2*)(sm + GW_HI + off) = make_uint2(h2u(wh01), h2u(wh23));
        *(uint2*)(sm + GW_LO + off) = make_uint2(h2u(wl01), h2u(wl23));
    }
    __syncthreads();

    int mwarp = (wid >> 2) * 64;
    int nwarp = (wid & 3) * 32;
    uint32_t axhi = sb + GX_HI + (uint32_t)(mwarp + (lane & 15)) * GSTR + (lane >> 4) * 16;
    uint32_t axlo = axhi + (GX_LO - GX_HI);
    uint32_t bwhi = sb + GW_HI +
        (uint32_t)(nwarp + (lane & 7) + ((lane >> 4) & 1) * 8) * GSTR +
        ((lane >> 3) & 1) * 16;
    uint32_t bwlo = bwhi + (GW_LO - GW_HI);

    float acc[4][4][4];
    #pragma unroll
    for (int mi = 0; mi < 4; mi++)
        #pragma unroll
        for (int n8 = 0; n8 < 4; n8++)
            #pragma unroll
            for (int x = 0; x < 4; x++) acc[mi][n8][x] = 0.f;

    #pragma unroll
    for (int kk = 0; kk < 8; kk++) {
        uint32_t ah[4][4], al[4][4];
        #pragma unroll
        for (int mi = 0; mi < 4; mi++) {
            ldsm_x4(ah[mi], axhi + mi * 16 * GSTR + kk * 32);
            ldsm_x4(al[mi], axlo + mi * 16 * GSTR + kk * 32);
        }
        #pragma unroll
        for (int nb = 0; nb < 2; nb++) {
            uint32_t bh[4], bl[4];
            ldsm_x4(bh, bwhi + nb * 16 * GSTR + kk * 32);
            ldsm_x4(bl, bwlo + nb * 16 * GSTR + kk * 32);
            #pragma unroll
            for (int mi = 0; mi < 4; mi++) {
                mma16816(acc[mi][nb * 2 + 0], ah[mi], bh + 0);
                mma16816(acc[mi][nb * 2 + 1], ah[mi], bh + 2);
                mma16816(acc[mi][nb * 2 + 0], al[mi], bh + 0);
                mma16816(acc[mi][nb * 2 + 1], al[mi], bh + 2);
                mma16816(acc[mi][nb * 2 + 0], ah[mi], bl + 0);
                mma16816(acc[mi][nb * 2 + 1], ah[mi], bl + 2);
            }
        }
    }

    #pragma unroll
    for (int mi = 0; mi < 4; mi++) {
        int r0 = mwarp + mi * 16 + (lane >> 2);
        #pragma unroll
        for (int n8 = 0; n8 < 4; n8++) {
            int col = nwarp + n8 * 8 + (lane & 3) * 2;
            float b0 = __ldg(bias + col), b1 = __ldg(bias + col + 1);
            __half2 o0 = __floats2half2_rn(acc[mi][n8][0] + b0, acc[mi][n8][1] + b1);
            __half2 o1 = __floats2half2_rn(acc[mi][n8][2] + b0, acc[mi][n8][3] + b1);
            *(uint32_t*)(outh + (size_t)(i0 + r0) * FF + col) = h2u(o0);
            *(uint32_t*)(outh + (size_t)(i0 + r0 + 8) * FF + col) = h2u(o1);
        }
    }
}

// ---------------- kernel 3b: convert Wo to fp16 hi/lo ----------------
__global__ void k_wo(const float* __restrict__ Wo) {
    int t = threadIdx.x;  // 256
    #pragma unroll
    for (int kk = 0; kk < 16; kk++) {
        int e = t + kk * 256;                 // float4 index, 4096 total
        float4 w = ((const float4*)Wo)[e];
        __half2 h01 = __floats2half2_rn(w.x, w.y);
        __half2 h23 = __floats2half2_rn(w.z, w.w);
        float2 f01 = __half22float2(h01), f23 = __half22float2(h23);
        __half2 l01 = __floats2half2_rn(w.x - f01.x, w.y - f01.y);
        __half2 l23 = __floats2half2_rn(w.z - f23.x, w.w - f23.y);
        *(uint2*)(g_woh + (size_t)e * 4) = make_uint2(h2u(h01), h2u(h23));
        *(uint2*)(g_wol + (size_t)e * 4) = make_uint2(h2u(l01), h2u(l23));
    }
}

// ---------------- kernel 4: dual-pipeline attn + fused output proj ---------
#define PSTRIDE 144
#define PBUF 18432
#define VSTRIDE 272
#define VBUF 17408
#define PH_BASE 0            // 4 x PBUF = 73728 (also: mbuf, then Wo hi/lo in epilogue)
#define VH_BASE 73728        // 4 x VBUF = 69632 (also: H hi/lo in epilogue)
#define E2_OFF  143360
#define RS_OFF  176128
#define IV_OFF  178176
#define SM_TOTAL 178688
#define MRG_STRIDE 132
#define ESTR 272             // epilogue row stride (bytes)

__global__ void __launch_bounds__(512, 1)
k_attn_mma(float* __restrict__ out) {
    extern __shared__ char sm[];
    int t = threadIdx.x;
    int lane = t & 31, wid = t >> 5;
    int g = wid >> 3;
    int w8 = wid & 7;
    int t256 = t & 255;
    int b = blockIdx.y;
    int it0 = blockIdx.x * 128;

    int mwarp = (w8 >> 2) * 64;
    int nwarp = (w8 & 3) * 32;

    uint32_t sbase = smem_u32(sm);
    uint32_t pgbase = sbase + PH_BASE + g * 2 * PBUF;
    uint32_t vgbase = sbase + VH_BASE + g * 2 * VBUF;
    uint32_t aoff = pgbase + (uint32_t)(mwarp + (lane & 15)) * PSTRIDE + (lane >> 4) * 16;
    uint32_t boff = vgbase + (uint32_t)(lane & 15) * VSTRIDE + (nwarp + (lane >> 4) * 8) * 2;

    int prow = t256 >> 1;
    int jh = (t256 & 1) * 32;
    float2 e1 = g_e1[b * NN + it0 + prow];
    float ea = e1.x, ea2 = e1.y;
    const uint32_t* maskp = g_adjbits + (size_t)(b * NN + it0 + prow) * (NN / 32) + (t256 & 1);
    const __half* vph = g_vph + (size_t)b * NN * FF;
    char* pdstH = sm + PH_BASE + g * 2 * PBUF + prow * PSTRIDE + jh * 2;
    const float4* e2q = (const float4*)(sm + E2_OFF) + (t256 & 1) * 16;

    int vr = t256 >> 2, vs = t256 & 3;
    uint32_t vdst = vgbase + vr * VSTRIDE + vs * 64;
    const __half* vsrc0 = vph + (size_t)vr * FF + vs * 32;

    {
        float4* d = (float4*)(sm + E2_OFF);
        const float4* s = (const float4*)(g_e2 + b * NN);
        #pragma unroll
        for (int kk = 0; kk < 4; kk++) d[t + kk * 512] = s[t + kk * 512];
    }

    float acc[4][4][4];
    #pragma unroll
    for (int mi = 0; mi < 4; mi++)
        #pragma unroll
        for (int n8 = 0; n8 < 4; n8++)
            #pragma unroll
            for (int x = 0; x < 4; x++) acc[mi][n8][x] = 0.f;
    float rs = 0.f;

    uint2 hiR[8];

    auto genP = [&](int c, uint32_t mask) {
        #pragma unroll
        for (int qq = 0; qq < 8; qq++) {
            float4 A  = e2q[c * 32 + qq * 2];
            float4 Bq = e2q[c * 32 + qq * 2 + 1];
            float p0 = (mask >> (qq * 4 + 0)) & 1u ? fmaxf(ea * A.x,  ea2 * A.y)  : 0.f;
            float p1 = (mask >> (qq * 4 + 1)) & 1u ? fmaxf(ea * A.z,  ea2 * A.w)  : 0.f;
            float p2 = (mask >> (qq * 4 + 2)) & 1u ? fmaxf(ea * Bq.x, ea2 * Bq.y) : 0.f;
            float p3 = (mask >> (qq * 4 + 3)) & 1u ? fmaxf(ea * Bq.z, ea2 * Bq.w) : 0.f;
            rs += (p0 + p1) + (p2 + p3);
            __half2 h01 = __floats2half2_rn(p0, p1);
            __half2 h23 = __floats2half2_rn(p2, p3);
            hiR[qq] = make_uint2(h2u(h01), h2u(h23));
        }
    };
    auto storeP = [&](int buf) {
        char* dh = pdstH + buf * PBUF;
        #pragma unroll
        for (int qq = 0; qq < 8; qq++)
            *(uint2*)(dh + qq * 8) = hiR[qq];
    };
    auto loadV = [&](int buf, int j0) {
        const __half* s = vsrc0 + (size_t)j0 * FF;
        uint32_t d = vdst + buf * VBUF;
        #pragma unroll
        for (int kk = 0; kk < 4; kk++)
            cp16(d + kk * 16, s + kk * 8);
        CP_COMMIT();
    };

    uint32_t mA = __ldg(maskp + 2 * g);
    uint32_t mB = __ldg(maskp + 2 * (g + 2));
    loadV(0, g * KC);
    __syncthreads();
    genP(g, mA);
    storeP(0);
    CP_WAIT0();
    BAR_G(g + 1);

    const int NIT = NN / KC / 2;
    for (int i = 0; i < NIT; i++) {
        int c = 2 * i + g;
        int buf = i & 1, nbuf = buf ^ 1;
        bool has_next = (i + 1) < NIT;
        uint32_t mC = 0;
        if (i + 2 < NIT) mC = __ldg(maskp + 2 * (c + 4));
        if (has_next) {
            loadV(nbuf, (c + 2) * KC);
            genP(c + 2, mB);
        }
        uint32_t pb = aoff + buf * PBUF;
        uint32_t vb = boff + buf * VBUF;
        #pragma unroll
        for (int kk = 0; kk < 4; kk++) {
            uint32_t ah[4][4];
            #pragma unroll
            for (int mi = 0; mi < 4; mi++)
                ldsm_x4(ah[mi], pb + mi * 16 * PSTRIDE + kk * 32);
            #pragma unroll
            for (int nb = 0; nb < 2; nb++) {
                uint32_t bh[4];
                ldsm_x4_t(bh, vb + kk * 16 * VSTRIDE + nb * 32);
                #pragma unroll
                for (int mi = 0; mi < 4; mi++) {
                    mma16816(acc[mi][nb * 2 + 0], ah[mi], bh + 0);
                    mma16816(acc[mi][nb * 2 + 1], ah[mi], bh + 2);
                }
            }
        }
        if (has_next) storeP(nbuf);
        mB = mC;
        CP_WAIT0();
        BAR_G(g + 1);
    }

    // ======== epilogue: normalize + fused h @ Wo^T (leaky) ========
    ((float*)(sm + RS_OFF))[g * 256 + t256] = rs;
    __syncthreads();
    if (t < 128) {
        const float* rss = (const float*)(sm + RS_OFF);
        float s = (rss[2 * t] + rss[2 * t + 1]) + (rss[256 + 2 * t] + rss[256 + 2 * t + 1]);
        ((float*)(sm + IV_OFF))[t] = 1.0f / s;
    }
    // g1 partial acc -> mbuf (P area)
    float* mbuf = (float*)sm;
    if (g == 1) {
        #pragma unroll
        for (int mi = 0; mi < 4; mi++) {
            int r0 = mwarp + mi * 16 + (lane >> 2);
            #pragma unroll
            for (int n8 = 0; n8 < 4; n8++) {
                int col = nwarp + n8 * 8 + (lane & 3) * 2;
                *(float2*)&mbuf[r0 * MRG_STRIDE + col] =
                    make_float2(acc[mi][n8][0], acc[mi][n8][1]);
                *(float2*)&mbuf[(r0 + 8) * MRG_STRIDE + col] =
                    make_float2(acc[mi][n8][2], acc[mi][n8][3]);
            }
        }
    }
    __syncthreads();
    // g0: merge + normalize -> fp16 hi/lo H in V area
    if (g == 0) {
        const float* inv = (const float*)(sm + IV_OFF);
        #pragma unroll
        for (int mi = 0; mi < 4; mi++) {
            int r0 = mwarp + mi * 16 + (lane >> 2);
            float iv0 = inv[r0], iv1 = inv[r0 + 8];
            #pragma unroll
            for (int n8 = 0; n8 < 4; n8++) {
                int col = nwarp + n8 * 8 + (lane & 3) * 2;
                float2 m0 = *(const float2*)&mbuf[r0 * MRG_STRIDE + col];
                float2 m1 = *(const float2*)&mbuf[(r0 + 8) * MRG_STRIDE + col];
                float h00 = (acc[0 + mi][n8][0] + m0.x) * iv0;
                float h01v = (acc[mi][n8][1] + m0.y) * iv0;
                float h10 = (acc[mi][n8][2] + m1.x) * iv1;
                float h11 = (acc[mi][n8][3] + m1.y) * iv1;
                __half2 hh0 = __floats2half2_rn(h00, h01v);
                __half2 hh1 = __floats2half2_rn(h10, h11);
                float2 hf0 = __half22float2(hh0), hf1 = __half22float2(hh1);
                __half2 hl0 = __floats2half2_rn(h00 - hf0.x, h01v - hf0.y);
                __half2 hl1 = __floats2half2_rn(h10 - hf1.x, h11 - hf1.y);
                *(uint32_t*)(sm + VH_BASE + r0 * ESTR + col * 2) = h2u(hh0);
                *(uint32_t*)(sm + VH_BASE + (r0 + 8) * ESTR + col * 2) = h2u(hh1);
                *(uint32_t*)(sm + VH_BASE + 34816 + r0 * ESTR + col * 2) = h2u(hl0);
                *(uint32_t*)(sm + VH_BASE + 34816 + (r0 + 8) * ESTR + col * 2) = h2u(hl1);
            }
        }
    }
    __syncthreads();
    // all: stage Wo hi/lo into P area via cp.async
    #pragma unroll
    for (int kk = 0; kk < 4; kk++) {
        int id = t + kk * 512;           // 2048 chunks per array
        int row = id >> 4, c = id & 15;
        cp16(sbase + row * ESTR + c * 16, g_woh + (size_t)row * FF + c * 8);
        cp16(sbase + 34816 + row * ESTR + c * 16, g_wol + (size_t)row * FF + c * 8);
    }
    CP_COMMIT();
    CP_WAIT0();
    __syncthreads();

    // epilogue MMA: 16 warps, 4x4 grid of 32x32 tiles, K=128, 3 passes
    {
        int em = (wid >> 2) * 32;
        int en = (wid & 3) * 32;
        uint32_t ahh = sbase + VH_BASE + (uint32_t)(em + (lane & 15)) * ESTR + (lane >> 4) * 16;
        uint32_t ahl = ahh + 34816;
        uint32_t bwh = sbase + (uint32_t)(en + (lane & 7) + ((lane >> 4) & 1) * 8) * ESTR +
                       ((lane >> 3) & 1) * 16;
        uint32_t bwl = bwh + 34816;

        float o2[2][4][4];
        #pragma unroll
        for (int mi = 0; mi < 2; mi++)
            #pragma unroll
            for (int n8 = 0; n8 < 4; n8++)
                #pragma unroll
                for (int x = 0; x < 4; x++) o2[mi][n8][x] = 0.f;

        #pragma unroll
        for (int kk = 0; kk < 8; kk++) {
            uint32_t ah[2][4], al[2][4];
            #pragma unroll
            for (int mi = 0; mi < 2; mi++) {
                ldsm_x4(ah[mi], ahh + mi * 16 * ESTR + kk * 32);
                ldsm_x4(al[mi], ahl + mi * 16 * ESTR + kk * 32);
            }
            #pragma unroll
            for (int nb = 0; nb < 2; nb++) {
                uint32_t bh[4], bl[4];
                ldsm_x4(bh, bwh + nb * 16 * ESTR + kk * 32);
                ldsm_x4(bl, bwl + nb * 16 * ESTR + kk * 32);
                #pragma unroll
                for (int mi = 0; mi < 2; mi++) {
                    mma16816(o2[mi][nb * 2 + 0], ah[mi], bh + 0);
                    mma16816(o2[mi][nb * 2 + 1], ah[mi], bh + 2);
                    mma16816(o2[mi][nb * 2 + 0], al[mi], bh + 0);
                    mma16816(o2[mi][nb * 2 + 1], al[mi], bh + 2);
                    mma16816(o2[mi][nb * 2 + 0], ah[mi], bl + 0);
                    mma16816(o2[mi][nb * 2 + 1], ah[mi], bl + 2);
                }
            }
        }

        #pragma unroll
        for (int mi = 0; mi < 2; mi++) {
            int r0 = em + mi * 16 + (lane >> 2);
            #pragma unroll
            for (int n8 = 0; n8 < 4; n8++) {
                int col = en + n8 * 8 + (lane & 3) * 2;
                float2 v0 = make_float2(leaky(o2[mi][n8][0]), leaky(o2[mi][n8][1]));
                float2 v1 = make_float2(leaky(o2[mi][n8][2]), leaky(o2[mi][n8][3]));
                *(float2*)(out + (size_t)(b * NN + it0 + r0) * FF + col) = v0;
                *(float2*)(out + (size_t)(b * NN + it0 + r0 + 8) * FF + col) = v1;
            }
        }
    }
}

// ---------------- launch ----------------
extern "C" void kernel_launch(void* const* d_in, const int* in_sizes, int n_in,
                              void* d_out, int out_size) {
    const float* q    = (const float*)d_in[0];
    const float* k    = (const float*)d_in[1];
    const float* v    = (const float*)d_in[2];
    const int*   adj  = (const int*)  d_in[3];
    const float* Wq_w = (const float*)d_in[4];
    const float* Wq_b = (const float*)d_in[5];
    const float* Wk_w = (const float*)d_in[6];
    const float* Wk_b = (const float*)d_in[7];
    const float* Wv_w = (const float*)d_in[8];
    const float* Wv_b = (const float*)d_in[9];
    const float* a    = (const float*)d_in[10];
    const float* Wo_w = (const float*)d_in[11];
    float* out = (float*)d_out;

    void* vph_ptr = nullptr;
    cudaGetSymbolAddress(&vph_ptr, g_vph);

    static cudaStream_t s1 = nullptr;
    static cudaEvent_t evFork = nullptr, evJoin = nullptr;
    if (!s1) {
        cudaStreamCreateWithFlags(&s1, cudaStreamNonBlocking);
        cudaEventCreateWithFlags(&evFork, cudaEventDisableTiming);
        cudaEventCreateWithFlags(&evJoin, cudaEventDisableTiming);
    }

    cudaFuncSetAttribute(k_attn_mma, cudaFuncAttributeMaxDynamicSharedMemorySize, SM_TOTAL);
    cudaFuncSetAttribute(k_gemm_tc, cudaFuncAttributeMaxDynamicSharedMemorySize, G_TOTAL);

    cudaEventRecord(evFork, 0);
    cudaStreamWaitEvent(s1, evFork, 0);
    k_pack<<<(BB * NN * NN) / (256 * 8), 256, 0, s1>>>(adj);

    k_prep<<<1, 128>>>(Wq_w, Wq_b, Wk_w, Wk_b, a);
    k_wh<<<(2 * BB * NN) / 8, 256>>>(q, k);
    k_gemm_tc<<<BB * NN / 128, 256, G_TOTAL>>>(v, Wv_w, Wv_b, (__half*)vph_ptr);
    k_wo<<<1, 256>>>(Wo_w);

    cudaEventRecord(evJoin, s1);
    cudaStreamWaitEvent(0, evJoin, 0);

    {
        dim3 grid(NN / 128, BB);
        k_attn_mma<<<grid, 512, SM_TOTAL>>>(out);
    }
}

// round 14
// speedup vs baseline: 1.5393x; 1.0434x over previous
#include <cuda_runtime.h>
#include <cuda_fp16.h>
#include <cstdint>

#define BB 4
#define NN 4096
#define FF 128
#define ALPHA 0.1f
#define KC 64

// ---------------- device scratch ----------------
__device__ float g_w1[FF], g_w2[FF], g_c[2];
__device__ __align__(16) float2 g_e1[BB * NN];
__device__ __align__(16) float2 g_e2[BB * NN];
__device__ __align__(16) __half g_vph[BB * NN * FF];            // fp16 [b][j][f]
__device__ __align__(16) __half g_woh[FF * FF];
__device__ __align__(16) __half g_wol[FF * FF];
__device__ __align__(16) uint32_t g_adjbits[BB * NN * (NN/32)];

__device__ __forceinline__ float leaky(float x) { return fmaxf(x, ALPHA * x); }

// ---------------- mma.sync helpers ----------------
__device__ __forceinline__ void mma16816(float* d, const uint32_t* a, const uint32_t* b) {
    asm volatile("mma.sync.aligned.m16n8k16.row.col.f32.f16.f16.f32 "
        "{%0,%1,%2,%3},{%4,%5,%6,%7},{%8,%9},{%0,%1,%2,%3};"
        : "+f"(d[0]), "+f"(d[1]), "+f"(d[2]), "+f"(d[3])
        : "r"(a[0]), "r"(a[1]), "r"(a[2]), "r"(a[3]), "r"(b[0]), "r"(b[1]));
}
__device__ __forceinline__ void ldsm_x4(uint32_t* r, uint32_t addr) {
    asm volatile("ldmatrix.sync.aligned.m8n8.x4.shared.b16 {%0,%1,%2,%3},[%4];"
        : "=r"(r[0]), "=r"(r[1]), "=r"(r[2]), "=r"(r[3]) : "r"(addr));
}
__device__ __forceinline__ void ldsm_x4_t(uint32_t* r, uint32_t addr) {
    asm volatile("ldmatrix.sync.aligned.m8n8.x4.trans.shared.b16 {%0,%1,%2,%3},[%4];"
        : "=r"(r[0]), "=r"(r[1]), "=r"(r[2]), "=r"(r[3]) : "r"(addr));
}
__device__ __forceinline__ uint32_t smem_u32(const void* p) {
    uint32_t a;
    asm("{ .reg .u64 t; cvta.to.shared.u64 t, %1; cvt.u32.u64 %0, t; }" : "=r"(a) : "l"(p));
    return a;
}
__device__ __forceinline__ void cp16(uint32_t dst, const void* src) {
    asm volatile("cp.async.cg.shared.global [%0], [%1], 16;" :: "r"(dst), "l"(src) : "memory");
}
#define CP_COMMIT() asm volatile("cp.async.commit_group;" ::: "memory")
#define CP_WAIT0()  asm volatile("cp.async.wait_group 0;" ::: "memory")
#define BARS(id)    asm volatile("bar.sync %0, 512;"   :: "r"(id) : "memory")
#define BARA(id)    asm volatile("bar.arrive %0, 512;" :: "r"(id) : "memory")
__device__ __forceinline__ uint32_t h2u(__half2 h) { return *(uint32_t*)&h; }

// ---------------- kernel 0: pack adj into bitmask ----------------
__global__ void __launch_bounds__(256) k_pack(const int* __restrict__ adj) {
    int t = blockIdx.x * 256 + threadIdx.x;
    const int4* p = (const int4*)adj + (size_t)t * 2;
    int4 a = p[0], b = p[1];
    uint32_t bits =
        (uint32_t)(a.x != 0)        | ((uint32_t)(a.y != 0) << 1) |
        ((uint32_t)(a.z != 0) << 2) | ((uint32_t)(a.w != 0) << 3) |
        ((uint32_t)(b.x != 0) << 4) | ((uint32_t)(b.y != 0) << 5) |
        ((uint32_t)(b.z != 0) << 6) | ((uint32_t)(b.w != 0) << 7);
    int lane = threadIdx.x & 31;
    uint32_t my = bits << ((lane & 3) * 8);
    my |= __shfl_xor_sync(0xffffffffu, my, 1);
    my |= __shfl_xor_sync(0xffffffffu, my, 2);
    if ((lane & 3) == 0) g_adjbits[t >> 2] = my;
}

// ---------------- kernel 1: fold a into Q/K projections ----------------
__global__ void k_prep(const float* __restrict__ Wq_w, const float* __restrict__ Wq_b,
                       const float* __restrict__ Wk_w, const float* __restrict__ Wk_b,
                       const float* __restrict__ a) {
    int f = threadIdx.x;
    float s1 = 0.f, s2 = 0.f;
    for (int o = 0; o < FF; o++) {
        s1 += Wq_w[o * FF + f] * a[o];
        s2 += Wk_w[o * FF + f] * a[FF + o];
    }
    g_w1[f] = s1; g_w2[f] = s2;
    if (f == 0) {
        float c1 = 0.f, c2 = 0.f;
        for (int o = 0; o < FF; o++) { c1 += Wq_b[o] * a[o]; c2 += Wk_b[o] * a[FF + o]; }
        g_c[0] = c1; g_c[1] = c2;
    }
}

// ---------------- kernel 2: Wh -> (exp(wh), exp(0.1 wh)) pairs -------------
__global__ void k_wh(const float* __restrict__ q, const float* __restrict__ k) {
    int warp = threadIdx.x >> 5, lane = threadIdx.x & 31;
    int row = blockIdx.x * 8 + warp;
    const float* src; const float* w; float c; float2* dst; int r;
    if (row < BB * NN) { src = q; w = g_w1; c = g_c[0]; dst = g_e1; r = row; }
    else               { src = k; w = g_w2; c = g_c[1]; dst = g_e2; r = row - BB * NN; }
    float4 x  = ((const float4*)(src + (size_t)r * FF))[lane];
    float4 ww = ((const float4*)w)[lane];
    float s = x.x * ww.x + x.y * ww.y + x.z * ww.z + x.w * ww.w;
    #pragma unroll
    for (int o = 16; o > 0; o >>= 1) s += __shfl_xor_sync(0xffffffffu, s, o);
    if (lane == 0) {
        float wh = s + c;
        dst[r] = make_float2(__expf(wh), __expf(ALPHA * wh));
    }
}

// ---------------- kernel 3: V projection, tensor core ----------------------
#define GSTR 272
#define GX_HI 0
#define GX_LO 34816
#define GW_HI 69632
#define GW_LO 104448
#define G_TOTAL 139264

__global__ void __launch_bounds__(256, 1)
k_gemm_tc(const float* __restrict__ in, const float* __restrict__ W,
          const float* __restrict__ bias, __half* __restrict__ outh) {
    extern __shared__ char sm[];
    int t = threadIdx.x, lane = t & 31, wid = t >> 5;
    int i0 = blockIdx.x * 128;
    uint32_t sb = smem_u32(sm);

    #pragma unroll
    for (int kk = 0; kk < 16; kk++) {
        int e = t + kk * 256;
        int row = e >> 5, f4 = e & 31;
        int off = row * GSTR + f4 * 8;
        float4 xv = *(const float4*)(in + (size_t)(i0 + row) * FF + f4 * 4);
        __half2 xh01 = __floats2half2_rn(xv.x, xv.y);
        __half2 xh23 = __floats2half2_rn(xv.z, xv.w);
        float2 xf01 = __half22float2(xh01), xf23 = __half22float2(xh23);
        __half2 xl01 = __floats2half2_rn(xv.x - xf01.x, xv.y - xf01.y);
        __half2 xl23 = __floats2half2_rn(xv.z - xf23.x, xv.w - xf23.y);
        *(uint2*)(sm + GX_HI + off) = make_uint2(h2u(xh01), h2u(xh23));
        *(uint2*)(sm + GX_LO + off) = make_uint2(h2u(xl01), h2u(xl23));
        float4 wv = *(const float4*)(W + (size_t)row * FF + f4 * 4);
        __half2 wh01 = __floats2half2_rn(wv.x, wv.y);
        __half2 wh23 = __floats2half2_rn(wv.z, wv.w);
        float2 wf01 = __half22float2(wh01), wf23 = __half22float2(wh23);
        __half2 wl01 = __floats2half2_rn(wv.x - wf01.x, wv.y - wf01.y);
        __half2 wl23 = __floats2half2_rn(wv.z - wf23.x, wv.w - wf23.y);
        *(uint2*)(sm + GW_HI + off) = make_uint2(h2u(wh01), h2u(wh23));
        *(uint2*)(sm + GW_LO + off) = make_uint2(h2u(wl01), h2u(wl23));
    }
    __syncthreads();

    int mwarp = (wid >> 2) * 64;
    int nwarp = (wid & 3) * 32;
    uint32_t axhi = sb + GX_HI + (uint32_t)(mwarp + (lane & 15)) * GSTR + (lane >> 4) * 16;
    uint32_t axlo = axhi + (GX_LO - GX_HI);
    uint32_t bwhi = sb + GW_HI +
        (uint32_t)(nwarp + (lane & 7) + ((lane >> 4) & 1) * 8) * GSTR +
        ((lane >> 3) & 1) * 16;
    uint32_t bwlo = bwhi + (GW_LO - GW_HI);

    float acc[4][4][4];
    #pragma unroll
    for (int mi = 0; mi < 4; mi++)
        #pragma unroll
        for (int n8 = 0; n8 < 4; n8++)
            #pragma unroll
            for (int x = 0; x < 4; x++) acc[mi][n8][x] = 0.f;

    #pragma unroll
    for (int kk = 0; kk < 8; kk++) {
        uint32_t ah[4][4], al[4][4];
        #pragma unroll
        for (int mi = 0; mi < 4; mi++) {
            ldsm_x4(ah[mi], axhi + mi * 16 * GSTR + kk * 32);
            ldsm_x4(al[mi], axlo + mi * 16 * GSTR + kk * 32);
        }
        #pragma unroll
        for (int nb = 0; nb < 2; nb++) {
            uint32_t bh[4], bl[4];
            ldsm_x4(bh, bwhi + nb * 16 * GSTR + kk * 32);
            ldsm_x4(bl, bwlo + nb * 16 * GSTR + kk * 32);
            #pragma unroll
            for (int mi = 0; mi < 4; mi++) {
                mma16816(acc[mi][nb * 2 + 0], ah[mi], bh + 0);
                mma16816(acc[mi][nb * 2 + 1], ah[mi], bh + 2);
                mma16816(acc[mi][nb * 2 + 0], al[mi], bh + 0);
                mma16816(acc[mi][nb * 2 + 1], al[mi], bh + 2);
                mma16816(acc[mi][nb * 2 + 0], ah[mi], bl + 0);
                mma16816(acc[mi][nb * 2 + 1], ah[mi], bl + 2);
            }
        }
    }

    #pragma unroll
    for (int mi = 0; mi < 4; mi++) {
        int r0 = mwarp + mi * 16 + (lane >> 2);
        #pragma unroll
        for (int n8 = 0; n8 < 4; n8++) {
            int col = nwarp + n8 * 8 + (lane & 3) * 2;
            float b0 = __ldg(bias + col), b1 = __ldg(bias + col + 1);
            __half2 o0 = __floats2half2_rn(acc[mi][n8][0] + b0, acc[mi][n8][1] + b1);
            __half2 o1 = __floats2half2_rn(acc[mi][n8][2] + b0, acc[mi][n8][3] + b1);
            *(uint32_t*)(outh + (size_t)(i0 + r0) * FF + col) = h2u(o0);
            *(uint32_t*)(outh + (size_t)(i0 + r0 + 8) * FF + col) = h2u(o1);
        }
    }
}

// ---------------- kernel 3b: convert Wo to fp16 hi/lo ----------------
__global__ void k_wo(const float* __restrict__ Wo) {
    int t = threadIdx.x;
    #pragma unroll
    for (int kk = 0; kk < 16; kk++) {
        int e = t + kk * 256;
        float4 w = ((const float4*)Wo)[e];
        __half2 h01 = __floats2half2_rn(w.x, w.y);
        __half2 h23 = __floats2half2_rn(w.z, w.w);
        float2 f01 = __half22float2(h01), f23 = __half22float2(h23);
        __half2 l01 = __floats2half2_rn(w.x - f01.x, w.y - f01.y);
        __half2 l23 = __floats2half2_rn(w.z - f23.x, w.w - f23.y);
        *(uint2*)(g_woh + (size_t)e * 4) = make_uint2(h2u(h01), h2u(h23));
        *(uint2*)(g_wol + (size_t)e * 4) = make_uint2(h2u(l01), h2u(l23));
    }
}

// ---------------- kernel 4: warp-specialized attn + fused output proj ------
// 512 threads: warps 0-7 = consumers (pure MMA), warps 8-15 = producers.
// 4-stage ring: stage s = [P 18432][V 17408]; full barriers ids 1-4, empty 5-8.
#define PSTRIDE 144
#define VSTRIDE 272
#define STAGE   35840        // P + V
#define VOFF    18432        // V offset within stage
#define NSTG    4
#define E2_OFF  143360       // 32768
#define RS_OFF  176128       // 1024 (256 floats)
#define IV_OFF  177152       // 512
#define SM_TOTAL 177664
#define ESTR 272             // epilogue row stride (bytes)
#define NCH (NN / KC)        // 64 chunks

__global__ void __launch_bounds__(512, 1)
k_attn_mma(float* __restrict__ out) {
    extern __shared__ char sm[];
    int t = threadIdx.x;
    int lane = t & 31, wid = t >> 5;
    int role = wid >> 3;             // 0 = consumer, 1 = producer
    int w8 = wid & 7;
    int t256 = t & 255;
    int b = blockIdx.y;
    int it0 = blockIdx.x * 128;

    uint32_t sbase = smem_u32(sm);

    // stage e2 pairs for this batch (2048 float4, all 512 threads)
    {
        float4* d = (float4*)(sm + E2_OFF);
        const float4* s = (const float4*)(g_e2 + b * NN);
        #pragma unroll
        for (int kk = 0; kk < 4; kk++) d[t + kk * 512] = s[t + kk * 512];
    }
    __syncthreads();

    if (role == 1) {
        // ================= PRODUCER =================
        int prow = t256 >> 1;
        int jh = (t256 & 1) * 32;
        float2 e1 = g_e1[b * NN + it0 + prow];
        float ea = e1.x, ea2 = e1.y;
        const uint32_t* maskp = g_adjbits + (size_t)(b * NN + it0 + prow) * (NN / 32) + (t256 & 1);
        const __half* vph = g_vph + (size_t)b * NN * FF;
        char* pdstH = sm + prow * PSTRIDE + jh * 2;
        const float4* e2q = (const float4*)(sm + E2_OFF) + (t256 & 1) * 16;
        int vr = t256 >> 2, vs = t256 & 3;
        uint32_t vdst = sbase + VOFF + vr * VSTRIDE + vs * 64;
        const __half* vsrc0 = vph + (size_t)vr * FF + vs * 32;

        float rs = 0.f;
        uint2 hiR[8];
        uint32_t mNext = __ldg(maskp);

        for (int c = 0; c < NCH; c++) {
            int s = c & 3;
            uint32_t m = mNext;
            if (c + 1 < NCH) mNext = __ldg(maskp + 2 * (c + 1));
            if (c >= NSTG) BARS(5 + s);
            // V load
            {
                const __half* src = vsrc0 + (size_t)c * KC * FF;
                uint32_t d = vdst + s * STAGE;
                #pragma unroll
                for (int kk = 0; kk < 4; kk++)
                    cp16(d + kk * 16, src + kk * 8);
                CP_COMMIT();
            }
            // P gen
            #pragma unroll
            for (int qq = 0; qq < 8; qq++) {
                float4 A  = e2q[c * 32 + qq * 2];
                float4 Bq = e2q[c * 32 + qq * 2 + 1];
                float p0 = (m >> (qq * 4 + 0)) & 1u ? fmaxf(ea * A.x,  ea2 * A.y)  : 0.f;
                float p1 = (m >> (qq * 4 + 1)) & 1u ? fmaxf(ea * A.z,  ea2 * A.w)  : 0.f;
                float p2 = (m >> (qq * 4 + 2)) & 1u ? fmaxf(ea * Bq.x, ea2 * Bq.y) : 0.f;
                float p3 = (m >> (qq * 4 + 3)) & 1u ? fmaxf(ea * Bq.z, ea2 * Bq.w) : 0.f;
                rs += (p0 + p1) + (p2 + p3);
                __half2 h01 = __floats2half2_rn(p0, p1);
                __half2 h23 = __floats2half2_rn(p2, p3);
                hiR[qq] = make_uint2(h2u(h01), h2u(h23));
            }
            {
                char* dh = pdstH + s * STAGE;
                #pragma unroll
                for (int qq = 0; qq < 8; qq++)
                    *(uint2*)(dh + qq * 8) = hiR[qq];
            }
            CP_WAIT0();
            BARA(1 + s);
        }
        ((float*)(sm + RS_OFF))[t256] = rs;
        __syncthreads();              // (A) all MMA done, rs staged
        // inverse normalizers by 128 producer threads
        if (t256 < 128) {
            const float* rss = (const float*)(sm + RS_OFF);
            ((float*)(sm + IV_OFF))[t256] = 1.0f / (rss[2 * t256] + rss[2 * t256 + 1]);
        }
        // stage Wo hi/lo into [69632 .. 139264) via cp.async (16 cp16 each)
        #pragma unroll
        for (int kk = 0; kk < 8; kk++) {
            int id = t256 + kk * 256;      // 2048 chunks of 16B per array
            int row = id >> 4, cc = id & 15;
            cp16(sbase + 69632 + row * ESTR + cc * 16, g_woh + (size_t)row * FF + cc * 8);
            cp16(sbase + 104448 + row * ESTR + cc * 16, g_wol + (size_t)row * FF + cc * 8);
        }
        CP_COMMIT();
        CP_WAIT0();
        __syncthreads();              // (B) H + inv + Wo ready
    } else {
        // ================= CONSUMER =================
        int mwarp = (w8 >> 2) * 64;
        int nwarp = (w8 & 3) * 32;
        uint32_t aoff = sbase + (uint32_t)(mwarp + (lane & 15)) * PSTRIDE + (lane >> 4) * 16;
        uint32_t boff = sbase + VOFF + (uint32_t)(lane & 15) * VSTRIDE + (nwarp + (lane >> 4) * 8) * 2;

        float acc[4][4][4];
        #pragma unroll
        for (int mi = 0; mi < 4; mi++)
            #pragma unroll
            for (int n8 = 0; n8 < 4; n8++)
                #pragma unroll
                for (int x = 0; x < 4; x++) acc[mi][n8][x] = 0.f;

        for (int c = 0; c < NCH; c++) {
            int s = c & 3;
            BARS(1 + s);
            uint32_t pb = aoff + s * STAGE;
            uint32_t vb = boff + s * STAGE;
            #pragma unroll
            for (int kk = 0; kk < 4; kk++) {
                uint32_t ah[4][4];
                #pragma unroll
                for (int mi = 0; mi < 4; mi++)
                    ldsm_x4(ah[mi], pb + mi * 16 * PSTRIDE + kk * 32);
                #pragma unroll
                for (int nb = 0; nb < 2; nb++) {
                    uint32_t bh[4];
                    ldsm_x4_t(bh, vb + kk * 16 * VSTRIDE + nb * 32);
                    #pragma unroll
                    for (int mi = 0; mi < 4; mi++) {
                        mma16816(acc[mi][nb * 2 + 0], ah[mi], bh + 0);
                        mma16816(acc[mi][nb * 2 + 1], ah[mi], bh + 2);
                    }
                }
            }
            if (c + NSTG < NCH) BARA(5 + s);
        }
        __syncthreads();              // (A)
        const float* inv = (const float*)(sm + IV_OFF);
        // this sync also publishes inv? inv written by producers between (A) and (B);
        // consumers read it below AFTER (B). Write normalized H hi/lo first needs inv,
        // so consumers wait at a light spin? No: producers compute inv right after (A),
        // but consumers need it now. Use second barrier: consumers write H AFTER (B)?
        // H must be written BEFORE (B). Resolve: producers compute inv BEFORE (A) is
        // not possible (rs staged at (A)). So: consumers compute inv themselves here
        // from rs (cheap, redundant across 128 threads):
        float invr[8];
        {
            const float* rss = (const float*)(sm + RS_OFF);
            #pragma unroll
            for (int mi = 0; mi < 4; mi++) {
                int r0 = (w8 >> 2) * 64 + mi * 16 + (lane >> 2);
                invr[mi * 2 + 0] = 1.0f / (rss[2 * r0] + rss[2 * r0 + 1]);
                invr[mi * 2 + 1] = 1.0f / (rss[2 * (r0 + 8)] + rss[2 * (r0 + 8) + 1]);
            }
        }
        int mwarp2 = (w8 >> 2) * 64, nwarp2 = (w8 & 3) * 32;
        #pragma unroll
        for (int mi = 0; mi < 4; mi++) {
            int r0 = mwarp2 + mi * 16 + (lane >> 2);
            float iv0 = invr[mi * 2 + 0], iv1 = invr[mi * 2 + 1];
            #pragma unroll
            for (int n8 = 0; n8 < 4; n8++) {
                int col = nwarp2 + n8 * 8 + (lane & 3) * 2;
                float h00 = acc[mi][n8][0] * iv0, h01v = acc[mi][n8][1] * iv0;
                float h10 = acc[mi][n8][2] * iv1, h11 = acc[mi][n8][3] * iv1;
                __half2 hh0 = __floats2half2_rn(h00, h01v);
                __half2 hh1 = __floats2half2_rn(h10, h11);
                float2 hf0 = __half22float2(hh0), hf1 = __half22float2(hh1);
                __half2 hl0 = __floats2half2_rn(h00 - hf0.x, h01v - hf0.y);
                __half2 hl1 = __floats2half2_rn(h10 - hf1.x, h11 - hf1.y);
                *(uint32_t*)(sm + r0 * ESTR + col * 2) = h2u(hh0);
                *(uint32_t*)(sm + (r0 + 8) * ESTR + col * 2) = h2u(hh1);
                *(uint32_t*)(sm + 34816 + r0 * ESTR + col * 2) = h2u(hl0);
                *(uint32_t*)(sm + 34816 + (r0 + 8) * ESTR + col * 2) = h2u(hl1);
            }
        }
        __syncthreads();              // (B)
    }

    // ======== fused output projection: all 16 warps ========
    {
        int em = (wid >> 2) * 32;
        int en = (wid & 3) * 32;
        uint32_t ahh = sbase + (uint32_t)(em + (lane & 15)) * ESTR + (lane >> 4) * 16;
        uint32_t ahl = ahh + 34816;
        uint32_t bwh = sbase + 69632 +
            (uint32_t)(en + (lane & 7) + ((lane >> 4) & 1) * 8) * ESTR +
            ((lane >> 3) & 1) * 16;
        uint32_t bwl = bwh + 34816;

        float o2[2][4][4];
        #pragma unroll
        for (int mi = 0; mi < 2; mi++)
            #pragma unroll
            for (int n8 = 0; n8 < 4; n8++)
                #pragma unroll
                for (int x = 0; x < 4; x++) o2[mi][n8][x] = 0.f;

        #pragma unroll
        for (int kk = 0; kk < 8; kk++) {
            uint32_t ah[2][4], al[2][4];
            #pragma unroll
            for (int mi = 0; mi < 2; mi++) {
                ldsm_x4(ah[mi], ahh + mi * 16 * ESTR + kk * 32);
                ldsm_x4(al[mi], ahl + mi * 16 * ESTR + kk * 32);
            }
            #pragma unroll
            for (int nb = 0; nb < 2; nb++) {
                uint32_t bh[4], bl[4];
                ldsm_x4(bh, bwh + nb * 16 * ESTR + kk * 32);
                ldsm_x4(bl, bwl + nb * 16 * ESTR + kk * 32);
                #pragma unroll
                for (int mi = 0; mi < 2; mi++) {
                    mma16816(o2[mi][nb * 2 + 0], ah[mi], bh + 0);
                    mma16816(o2[mi][nb * 2 + 1], ah[mi], bh + 2);
                    mma16816(o2[mi][nb * 2 + 0], al[mi], bh + 0);
                    mma16816(o2[mi][nb * 2 + 1], al[mi], bh + 2);
                    mma16816(o2[mi][nb * 2 + 0], ah[mi], bl + 0);
                    mma16816(o2[mi][nb * 2 + 1], ah[mi], bl + 2);
                }
            }
        }

        #pragma unroll
        for (int mi = 0; mi < 2; mi++) {
            int r0 = em + mi * 16 + (lane >> 2);
            #pragma unroll
            for (int n8 = 0; n8 < 4; n8++) {
                int col = en + n8 * 8 + (lane & 3) * 2;
                float2 v0 = make_float2(leaky(o2[mi][n8][0]), leaky(o2[mi][n8][1]));
                float2 v1 = make_float2(leaky(o2[mi][n8][2]), leaky(o2[mi][n8][3]));
                *(float2*)(out + (size_t)(b * NN + it0 + r0) * FF + col) = v0;
                *(float2*)(out + (size_t)(b * NN + it0 + r0 + 8) * FF + col) = v1;
            }
        }
    }
}

// ---------------- launch ----------------
extern "C" void kernel_launch(void* const* d_in, const int* in_sizes, int n_in,
                              void* d_out, int out_size) {
    const float* q    = (const float*)d_in[0];
    const float* k    = (const float*)d_in[1];
    const float* v    = (const float*)d_in[2];
    const int*   adj  = (const int*)  d_in[3];
    const float* Wq_w = (const float*)d_in[4];
    const float* Wq_b = (const float*)d_in[5];
    const float* Wk_w = (const float*)d_in[6];
    const float* Wk_b = (const float*)d_in[7];
    const float* Wv_w = (const float*)d_in[8];
    const float* Wv_b = (const float*)d_in[9];
    const float* a    = (const float*)d_in[10];
    const float* Wo_w = (const float*)d_in[11];
    float* out = (float*)d_out;

    void* vph_ptr = nullptr;
    cudaGetSymbolAddress(&vph_ptr, g_vph);

    static cudaStream_t s1 = nullptr;
    static cudaEvent_t evFork = nullptr, evJoin = nullptr;
    if (!s1) {
        cudaStreamCreateWithFlags(&s1, cudaStreamNonBlocking);
        cudaEventCreateWithFlags(&evFork, cudaEventDisableTiming);
        cudaEventCreateWithFlags(&evJoin, cudaEventDisableTiming);
    }

    cudaFuncSetAttribute(k_attn_mma, cudaFuncAttributeMaxDynamicSharedMemorySize, SM_TOTAL);
    cudaFuncSetAttribute(k_gemm_tc, cudaFuncAttributeMaxDynamicSharedMemorySize, G_TOTAL);

    cudaEventRecord(evFork, 0);
    cudaStreamWaitEvent(s1, evFork, 0);
    k_pack<<<(BB * NN * NN) / (256 * 8), 256, 0, s1>>>(adj);

    k_prep<<<1, 128>>>(Wq_w, Wq_b, Wk_w, Wk_b, a);
    k_wh<<<(2 * BB * NN) / 8, 256>>>(q, k);
    k_gemm_tc<<<BB * NN / 128, 256, G_TOTAL>>>(v, Wv_w, Wv_b, (__half*)vph_ptr);
    k_wo<<<1, 256>>>(Wo_w);

    cudaEventRecord(evJoin, s1);
    cudaStreamWaitEvent(0, evJoin, 0);

    {
        dim3 grid(NN / 128, BB);
        k_attn_mma<<<grid, 512, SM_TOTAL>>>(out);
    }
}